// round 1
// baseline (speedup 1.0000x reference)
#include <cuda_runtime.h>
#include <math.h>

#define NN      16384
#define BG      64
#define H       256
#define NHEADS  8
#define HD      32

// ---------------- scratch (device globals; no runtime allocation) ----------
__device__ float g_xn  [NN * H];        // graphnorm1 output
__device__ float g_qkv [NN * 3 * H];    // ragged qkv
__device__ float g_ctx [NN * H];        // attention context
__device__ float g_xmid[NN * H];        // x + attn_out
__device__ float g_xn2 [NN * H];        // graphnorm2 output
__device__ float g_hid [NN * 4 * H];    // ffn hidden
__device__ int   g_counts[BG];
__device__ int   g_starts[BG];

// ---------------- counts / starts ------------------------------------------
__global__ void count_kernel(const int* __restrict__ batch)
{
    __shared__ int s[BG];
    int t = threadIdx.x;
    if (t < BG) s[t] = 0;
    __syncthreads();
    for (int i = t; i < NN; i += blockDim.x) atomicAdd(&s[batch[i]], 1);
    __syncthreads();
    if (t == 0) {
        int acc = 0;
        for (int b = 0; b < BG; b++) { g_starts[b] = acc; g_counts[b] = s[b]; acc += s[b]; }
    }
}

// ---------------- GraphNorm: per-graph mean / unbiased std (+eps on std) ---
__global__ void graphnorm_kernel(const float* __restrict__ in,
                                 const float* __restrict__ w,
                                 const float* __restrict__ bias,
                                 float* __restrict__ out)
{
    int b = blockIdx.x;
    int f = threadIdx.x;                 // H = 256 threads, one feature each
    int c = g_counts[b];
    long s = g_starts[b];
    if (c == 0) return;
    const float* p = in + s * H + f;
    float sum = 0.f, sq = 0.f;
    for (int i = 0; i < c; i++) { float v = p[(long)i * H]; sum += v; sq += v * v; }
    float cf   = (float)c;
    float mean = sum / cf;
    float var  = fmaxf((sq - sum * sum / cf) / fmaxf(cf - 1.f, 1.f), 0.f);
    float inv  = 1.f / (sqrtf(var) + 1e-5f);
    float ww = w[f], bb = bias[f];
    float* q = out + s * H + f;
    for (int i = 0; i < c; i++)
        q[(long)i * H] = ww * ((p[(long)i * H] - mean) * inv) + bb;
}

// ---------------- SGEMM: C[M,Nc] = A[M,K] @ W[Nc,K]^T + bias (+gelu/+res) --
// BM=BN=128, BK=16, 256 threads, 8x8 per thread.
template<bool GELU, bool RES>
__global__ __launch_bounds__(256) void gemm_kernel(
    const float* __restrict__ A, const float* __restrict__ W,
    const float* __restrict__ bias, const float* __restrict__ res,
    float* __restrict__ C, int M, int Nc, int K)
{
    __shared__ float As[16][132];
    __shared__ float Bs[16][132];
    int tid = threadIdx.x;
    int tx = tid & 15, ty = tid >> 4;
    int m0 = blockIdx.y << 7, n0 = blockIdx.x << 7;

    float acc[8][8];
#pragma unroll
    for (int i = 0; i < 8; i++)
#pragma unroll
        for (int j = 0; j < 8; j++) acc[i][j] = 0.f;

    for (int k0 = 0; k0 < K; k0 += 16) {
#pragma unroll
        for (int l = 0; l < 2; l++) {
            int f   = tid + (l << 8);
            int row = f >> 2;
            int kc  = (f & 3) << 2;
            float4 va = *(const float4*)(A + (size_t)(m0 + row) * K + k0 + kc);
            As[kc    ][row] = va.x; As[kc + 1][row] = va.y;
            As[kc + 2][row] = va.z; As[kc + 3][row] = va.w;
            float4 vb = *(const float4*)(W + (size_t)(n0 + row) * K + k0 + kc);
            Bs[kc    ][row] = vb.x; Bs[kc + 1][row] = vb.y;
            Bs[kc + 2][row] = vb.z; Bs[kc + 3][row] = vb.w;
        }
        __syncthreads();
#pragma unroll
        for (int k = 0; k < 16; k++) {
            float a[8], b[8];
            *(float4*)(a)     = *(const float4*)&As[k][ty * 8];
            *(float4*)(a + 4) = *(const float4*)&As[k][ty * 8 + 4];
            *(float4*)(b)     = *(const float4*)&Bs[k][tx * 8];
            *(float4*)(b + 4) = *(const float4*)&Bs[k][tx * 8 + 4];
#pragma unroll
            for (int i = 0; i < 8; i++)
#pragma unroll
                for (int j = 0; j < 8; j++)
                    acc[i][j] = fmaf(a[i], b[j], acc[i][j]);
        }
        __syncthreads();
    }

#pragma unroll
    for (int i = 0; i < 8; i++) {
        int m = m0 + ty * 8 + i;
#pragma unroll
        for (int j = 0; j < 8; j++) {
            int n = n0 + tx * 8 + j;
            float v = acc[i][j] + bias[n];
            if (GELU) v = 0.5f * v * (1.f + erff(v * 0.70710678118654752f));
            if (RES)  v += res[(size_t)m * Nc + n];
            C[(size_t)m * Nc + n] = v;
        }
    }
}

// ---------------- Flash attention over ragged per-graph segments ------------
// grid = (8 q-tiles, NHEADS, BG); 256 threads = 16(tx: key/dim) x 16(ty: query)
__global__ __launch_bounds__(256) void attn_kernel(const float* __restrict__ qkv,
                                                   float* __restrict__ ctx)
{
    int b  = blockIdx.z, h = blockIdx.y, qt = blockIdx.x;
    int c  = g_counts[b];
    int s  = g_starts[b];
    int q0 = qt << 6;
    if (q0 >= c) return;

    int tid = threadIdx.x;
    int tx = tid & 15, ty = tid >> 4;

    __shared__ float Qt[HD][68];    // [d][q], q scaled by 1/sqrt(hd)
    __shared__ float Kt[HD][68];    // [d][k]
    __shared__ float Vs[64][34];    // [k][d]
    __shared__ float Ps[64][68];    // probs [q][k]

    const float scale = 0.17677669529663687f;   // 1/sqrt(32)

#pragma unroll
    for (int l = 0; l < 8; l++) {
        int e = tid + (l << 8);
        int row = e >> 5, d = e & 31;
        float v = (q0 + row < c)
            ? qkv[(size_t)(s + q0 + row) * (3 * H) + h * HD + d] * scale : 0.f;
        Qt[d][row] = v;
    }

    float m[4], lsum[4], o0[4], o1[4];
#pragma unroll
    for (int i = 0; i < 4; i++) { m[i] = -1e30f; lsum[i] = 0.f; o0[i] = 0.f; o1[i] = 0.f; }

    for (int k0 = 0; k0 < c; k0 += 64) {
        __syncthreads();
#pragma unroll
        for (int l = 0; l < 8; l++) {
            int e = tid + (l << 8);
            int row = e >> 5, d = e & 31;
            bool ok = (k0 + row < c);
            size_t base = (size_t)(s + k0 + row) * (3 * H) + h * HD + d;
            Kt[d][row] = ok ? qkv[base + H]     : 0.f;
            Vs[row][d] = ok ? qkv[base + 2 * H] : 0.f;
        }
        __syncthreads();

        float sc[4][4];
#pragma unroll
        for (int i = 0; i < 4; i++) { sc[i][0] = sc[i][1] = sc[i][2] = sc[i][3] = 0.f; }
#pragma unroll
        for (int d = 0; d < HD; d++) {
            float4 qa = *(const float4*)&Qt[d][ty * 4];
            float4 kb = *(const float4*)&Kt[d][tx * 4];
            float qv[4] = {qa.x, qa.y, qa.z, qa.w};
            float kv[4] = {kb.x, kb.y, kb.z, kb.w};
#pragma unroll
            for (int i = 0; i < 4; i++)
#pragma unroll
                for (int j = 0; j < 4; j++)
                    sc[i][j] = fmaf(qv[i], kv[j], sc[i][j]);
        }
        int kvalid = c - k0;
#pragma unroll
        for (int j = 0; j < 4; j++)
            if (tx * 4 + j >= kvalid) {
#pragma unroll
                for (int i = 0; i < 4; i++) sc[i][j] = -1e30f;
            }

#pragma unroll
        for (int i = 0; i < 4; i++) {
            float mx = fmaxf(fmaxf(sc[i][0], sc[i][1]), fmaxf(sc[i][2], sc[i][3]));
            mx = fmaxf(mx, __shfl_xor_sync(0xffffffffu, mx, 1));
            mx = fmaxf(mx, __shfl_xor_sync(0xffffffffu, mx, 2));
            mx = fmaxf(mx, __shfl_xor_sync(0xffffffffu, mx, 4));
            mx = fmaxf(mx, __shfl_xor_sync(0xffffffffu, mx, 8));
            float mnew  = fmaxf(m[i], mx);
            float alpha = __expf(m[i] - mnew);
            float ps = 0.f;
#pragma unroll
            for (int j = 0; j < 4; j++) {
                float p = __expf(sc[i][j] - mnew);
                Ps[ty * 4 + i][tx * 4 + j] = p;
                ps += p;
            }
            ps += __shfl_xor_sync(0xffffffffu, ps, 1);
            ps += __shfl_xor_sync(0xffffffffu, ps, 2);
            ps += __shfl_xor_sync(0xffffffffu, ps, 4);
            ps += __shfl_xor_sync(0xffffffffu, ps, 8);
            lsum[i] = lsum[i] * alpha + ps;
            o0[i] *= alpha; o1[i] *= alpha;
            m[i] = mnew;
        }
        __syncwarp();

#pragma unroll 4
        for (int kk = 0; kk < 64; kk++) {
            float2 v2 = *(const float2*)&Vs[kk][tx * 2];
#pragma unroll
            for (int i = 0; i < 4; i++) {
                float p = Ps[ty * 4 + i][kk];
                o0[i] = fmaf(p, v2.x, o0[i]);
                o1[i] = fmaf(p, v2.y, o1[i]);
            }
        }
    }

#pragma unroll
    for (int i = 0; i < 4; i++) {
        int q = q0 + ty * 4 + i;
        if (q < c) {
            float inv = 1.f / lsum[i];
            size_t base = (size_t)(s + q) * H + h * HD + tx * 2;
            ctx[base]     = o0[i] * inv;
            ctx[base + 1] = o1[i] * inv;
        }
    }
}

// ---------------- launch ----------------------------------------------------
extern "C" void kernel_launch(void* const* d_in, const int* in_sizes, int n_in,
                              void* d_out, int out_size)
{
    const float* x     = (const float*)d_in[0];
    const int*   batch = (const int*)d_in[1];
    // detect whether the scalar max_nodes is present as d_in[2]
    int base = (n_in >= 15 && in_sizes[2] == 1) ? 3 : 2;
    const float* n1w = (const float*)d_in[base + 0];
    const float* n1b = (const float*)d_in[base + 1];
    const float* iw  = (const float*)d_in[base + 2];
    const float* ib  = (const float*)d_in[base + 3];
    const float* ow  = (const float*)d_in[base + 4];
    const float* ob  = (const float*)d_in[base + 5];
    const float* n2w = (const float*)d_in[base + 6];
    const float* n2b = (const float*)d_in[base + 7];
    const float* w1  = (const float*)d_in[base + 8];
    const float* b1  = (const float*)d_in[base + 9];
    const float* w2  = (const float*)d_in[base + 10];
    const float* b2  = (const float*)d_in[base + 11];
    float* out = (float*)d_out;

    float *p_xn, *p_qkv, *p_ctx, *p_xmid, *p_xn2, *p_h;
    cudaGetSymbolAddress((void**)&p_xn,   g_xn);
    cudaGetSymbolAddress((void**)&p_qkv,  g_qkv);
    cudaGetSymbolAddress((void**)&p_ctx,  g_ctx);
    cudaGetSymbolAddress((void**)&p_xmid, g_xmid);
    cudaGetSymbolAddress((void**)&p_xn2,  g_xn2);
    cudaGetSymbolAddress((void**)&p_h,    g_hid);

    count_kernel<<<1, 256>>>(batch);
    graphnorm_kernel<<<BG, H>>>(x, n1w, n1b, p_xn);
    gemm_kernel<false, false><<<dim3(3 * H / 128, NN / 128), 256>>>(
        p_xn, iw, ib, nullptr, p_qkv, NN, 3 * H, H);
    attn_kernel<<<dim3(8, NHEADS, BG), 256>>>(p_qkv, p_ctx);
    gemm_kernel<false, true><<<dim3(H / 128, NN / 128), 256>>>(
        p_ctx, ow, ob, x, p_xmid, NN, H, H);
    graphnorm_kernel<<<BG, H>>>(p_xmid, n2w, n2b, p_xn2);
    gemm_kernel<true, false><<<dim3(4 * H / 128, NN / 128), 256>>>(
        p_xn2, w1, b1, nullptr, p_h, NN, 4 * H, H);
    gemm_kernel<false, true><<<dim3(H / 128, NN / 128), 256>>>(
        p_h, w2, b2, p_xmid, out, NN, H, 4 * H);
}

// round 4
// speedup vs baseline: 1.4643x; 1.4643x over previous
#include <cuda_runtime.h>
#include <cuda_bf16.h>
#include <math.h>
#include <stdint.h>

#define NN      16384
#define BG      64
#define H       256
#define NHEADS  8
#define HD      32

// ======================= scratch (device globals) ===========================
__device__ __nv_bfloat16 g_xn_hi[NN * H],      g_xn_lo[NN * H];
__device__ float         g_qkv[NN * 3 * H];
__device__ __nv_bfloat16 g_ctx_hi[NN * H],     g_ctx_lo[NN * H];
__device__ float         g_xmid[NN * H];
__device__ __nv_bfloat16 g_xn2_hi[NN * H],     g_xn2_lo[NN * H];
__device__ __nv_bfloat16 g_hid_hi[NN * 4 * H], g_hid_lo[NN * 4 * H];
__device__ __nv_bfloat16 g_wqkv_hi[3 * H * H], g_wqkv_lo[3 * H * H];
__device__ __nv_bfloat16 g_wout_hi[H * H],     g_wout_lo[H * H];
__device__ __nv_bfloat16 g_w1_hi[4 * H * H],   g_w1_lo[4 * H * H];
__device__ __nv_bfloat16 g_w2_hi[H * 4 * H],   g_w2_lo[H * 4 * H];
__device__ int g_counts[BG];
__device__ int g_starts[BG];

__device__ __forceinline__ void split_store(float v, __nv_bfloat16* hi, __nv_bfloat16* lo, size_t idx) {
    __nv_bfloat16 h = __float2bfloat16(v);
    hi[idx] = h;
    lo[idx] = __float2bfloat16(v - __bfloat162float(h));
}

__device__ __forceinline__ uint32_t smem_u32(const void* p) {
    uint32_t a;
    asm("{ .reg .u64 t; cvta.to.shared.u64 t, %1; cvt.u32.u64 %0, t; }" : "=r"(a) : "l"(p));
    return a;
}
#define CP_ASYNC16(dst, src) \
    asm volatile("cp.async.cg.shared.global [%0], [%1], 16;" :: "r"(dst), "l"(src))
#define CP_COMMIT() asm volatile("cp.async.commit_group;" ::: "memory")
#define CP_WAIT(n)  asm volatile("cp.async.wait_group %0;" :: "n"(n) : "memory")

__device__ __forceinline__ void mma16816(float* c, const uint32_t* a, const uint32_t* b) {
    asm volatile("mma.sync.aligned.m16n8k16.row.col.f32.bf16.bf16.f32 "
        "{%0,%1,%2,%3}, {%4,%5,%6,%7}, {%8,%9}, {%0,%1,%2,%3};"
        : "+f"(c[0]), "+f"(c[1]), "+f"(c[2]), "+f"(c[3])
        : "r"(a[0]), "r"(a[1]), "r"(a[2]), "r"(a[3]), "r"(b[0]), "r"(b[1]));
}

// ---------------- counts / starts ------------------------------------------
__global__ void count_kernel(const int* __restrict__ batch)
{
    __shared__ int s[BG];
    int t = threadIdx.x;
    if (t < BG) s[t] = 0;
    __syncthreads();
    for (int i = t; i < NN; i += blockDim.x) atomicAdd(&s[batch[i]], 1);
    __syncthreads();
    if (t == 0) {
        int acc = 0;
        for (int b = 0; b < BG; b++) { g_starts[b] = acc; g_counts[b] = s[b]; acc += s[b]; }
    }
}

// ---------------- weight fp32 -> bf16 hi/lo ---------------------------------
__global__ void convert_kernel(const float* __restrict__ src,
                               __nv_bfloat16* __restrict__ hi,
                               __nv_bfloat16* __restrict__ lo, int n)
{
    int i = blockIdx.x * blockDim.x + threadIdx.x;
    if (i < n) split_store(src[i], hi, lo, i);
}

// ---------------- GraphNorm -> bf16 hi/lo -----------------------------------
__global__ void graphnorm_kernel(const float* __restrict__ in,
                                 const float* __restrict__ w,
                                 const float* __restrict__ bias,
                                 __nv_bfloat16* __restrict__ oh,
                                 __nv_bfloat16* __restrict__ ol)
{
    int b = blockIdx.x;
    int f = threadIdx.x;
    int c = g_counts[b];
    long s = g_starts[b];
    if (c == 0) return;
    const float* p = in + s * H + f;
    float sum = 0.f, sq = 0.f;
    for (int i = 0; i < c; i++) { float v = p[(long)i * H]; sum += v; sq += v * v; }
    float cf   = (float)c;
    float mean = sum / cf;
    float var  = fmaxf((sq - sum * sum / cf) / fmaxf(cf - 1.f, 1.f), 0.f);
    float inv  = 1.f / (sqrtf(var) + 1e-5f);
    float ww = w[f], bb = bias[f];
    for (int i = 0; i < c; i++) {
        float v = ww * ((p[(long)i * H] - mean) * inv) + bb;
        split_store(v, oh, ol, (size_t)(s + i) * H + f);
    }
}

// ======================= HMMA GEMM (bf16x3) =================================
// C[M,Nc] = A[M,K] @ W[Nc,K]^T + bias (+res / +gelu)
// CTA tile 128x128, BK=32, 8 warps each 64x32, double-buffered cp.async.
// smem per stage: Ah | Al | Bh | Bl, each 128 rows x 80B (32 bf16 + 16B pad).
// SROW=80: 16B-aligned rows for cp.async, and conflict-free fragment LDS
// (word index row*20+pair mod 32 hits all 32 banks across the 8x4 lane grid).
#define SROW   80
#define ARR_SZ (128 * SROW)        // 10240
#define STG_SZ (4 * ARR_SZ)        // 40960
#define GEMM_SMEM (2 * STG_SZ)     // 81920

template<int EPI>   // 0: bias->f32   1: bias+res->f32   2: gelu(bias)->bf16 hi/lo
__global__ __launch_bounds__(256, 1) void hgemm_kernel(
    const __nv_bfloat16* __restrict__ Ah, const __nv_bfloat16* __restrict__ Al,
    const __nv_bfloat16* __restrict__ Bh, const __nv_bfloat16* __restrict__ Bl,
    const float* __restrict__ bias, const float* __restrict__ res,
    float* __restrict__ Cf, __nv_bfloat16* __restrict__ Ch, __nv_bfloat16* __restrict__ Cl,
    int Nc, int K)
{
    extern __shared__ char sm[];
    const int tid  = threadIdx.x;
    const int wid  = tid >> 5, lane = tid & 31;
    const int quad = lane >> 2, pair = lane & 3;
    const int m0 = blockIdx.y << 7, n0 = blockIdx.x << 7;
    const int wm = (wid & 1) << 6;        // warp m-offset within tile
    const int wn = (wid >> 1) << 5;       // warp n-offset within tile
    const uint32_t smb = smem_u32(sm);

    const char* gsrc[4] = { (const char*)Ah, (const char*)Al, (const char*)Bh, (const char*)Bl };

    float acc[4][4][4];
    #pragma unroll
    for (int a = 0; a < 4; a++)
        #pragma unroll
        for (int b = 0; b < 4; b++)
            #pragma unroll
            for (int r = 0; r < 4; r++) acc[a][b][r] = 0.f;

    const int nchunk = K >> 5;

    // ---- async load of one K-chunk (32 cols) into a stage ----
    auto load_chunk = [&](int stage, int k0) {
        uint32_t sb = smb + stage * STG_SZ;
        #pragma unroll
        for (int t = 0; t < 8; t++) {
            int task = tid + (t << 8);          // 0..2047
            int arr  = task >> 9;               // 512 tasks per array
            int idx  = task & 511;
            int row  = idx >> 2, ch = idx & 3;  // 4 x 16B per 64B row payload
            int r0   = (arr < 2) ? m0 : n0;
            const char* src = gsrc[arr] + ((size_t)(r0 + row) * K + k0 + ch * 8) * 2;
            uint32_t dst = sb + arr * ARR_SZ + row * SROW + ch * 16;
            CP_ASYNC16(dst, src);
        }
        CP_COMMIT();
    };

    load_chunk(0, 0);
    for (int c = 0; c < nchunk; c++) {
        if (c + 1 < nchunk) { load_chunk((c + 1) & 1, (c + 1) << 5); CP_WAIT(1); }
        else                { CP_WAIT(0); }
        __syncthreads();

        const int stg = (c & 1) * STG_SZ;
        #pragma unroll
        for (int ks = 0; ks < 2; ks++) {
            const int kb = ks * 32 + pair * 4;
            uint32_t afh[4][4], afl[4][4], bfh[4][2], bfl[4][2];
            #pragma unroll
            for (int mt = 0; mt < 4; mt++) {
                int o = stg + (wm + mt * 16 + quad) * SROW + kb;
                afh[mt][0] = *(const uint32_t*)(sm + o);
                afh[mt][1] = *(const uint32_t*)(sm + o + 8 * SROW);
                afh[mt][2] = *(const uint32_t*)(sm + o + 16);
                afh[mt][3] = *(const uint32_t*)(sm + o + 8 * SROW + 16);
                afl[mt][0] = *(const uint32_t*)(sm + o + ARR_SZ);
                afl[mt][1] = *(const uint32_t*)(sm + o + ARR_SZ + 8 * SROW);
                afl[mt][2] = *(const uint32_t*)(sm + o + ARR_SZ + 16);
                afl[mt][3] = *(const uint32_t*)(sm + o + ARR_SZ + 8 * SROW + 16);
            }
            #pragma unroll
            for (int nt = 0; nt < 4; nt++) {
                int o = stg + 2 * ARR_SZ + (wn + nt * 8 + quad) * SROW + kb;
                bfh[nt][0] = *(const uint32_t*)(sm + o);
                bfh[nt][1] = *(const uint32_t*)(sm + o + 16);
                bfl[nt][0] = *(const uint32_t*)(sm + o + ARR_SZ);
                bfl[nt][1] = *(const uint32_t*)(sm + o + ARR_SZ + 16);
            }
            #pragma unroll
            for (int mt = 0; mt < 4; mt++)
                #pragma unroll
                for (int nt = 0; nt < 4; nt++) {
                    mma16816(acc[mt][nt], afh[mt], bfh[nt]);
                    mma16816(acc[mt][nt], afl[mt], bfh[nt]);
                    mma16816(acc[mt][nt], afh[mt], bfl[nt]);
                }
        }
        __syncthreads();
    }

    // ---- epilogue ----
    #pragma unroll
    for (int mt = 0; mt < 4; mt++) {
        int row0 = m0 + wm + mt * 16 + quad;
        int row1 = row0 + 8;
        #pragma unroll
        for (int nt = 0; nt < 4; nt++) {
            int col = n0 + wn + nt * 8 + pair * 2;
            float b0v = bias[col], b1v = bias[col + 1];
            float v00 = acc[mt][nt][0] + b0v, v01 = acc[mt][nt][1] + b1v;
            float v10 = acc[mt][nt][2] + b0v, v11 = acc[mt][nt][3] + b1v;
            if (EPI == 2) {
                v00 = 0.5f * v00 * (1.f + erff(v00 * 0.70710678118654752f));
                v01 = 0.5f * v01 * (1.f + erff(v01 * 0.70710678118654752f));
                v10 = 0.5f * v10 * (1.f + erff(v10 * 0.70710678118654752f));
                v11 = 0.5f * v11 * (1.f + erff(v11 * 0.70710678118654752f));
                split_store(v00, Ch, Cl, (size_t)row0 * Nc + col);
                split_store(v01, Ch, Cl, (size_t)row0 * Nc + col + 1);
                split_store(v10, Ch, Cl, (size_t)row1 * Nc + col);
                split_store(v11, Ch, Cl, (size_t)row1 * Nc + col + 1);
            } else {
                if (EPI == 1) {
                    v00 += res[(size_t)row0 * Nc + col];
                    v01 += res[(size_t)row0 * Nc + col + 1];
                    v10 += res[(size_t)row1 * Nc + col];
                    v11 += res[(size_t)row1 * Nc + col + 1];
                }
                *(float2*)(Cf + (size_t)row0 * Nc + col) = make_float2(v00, v01);
                *(float2*)(Cf + (size_t)row1 * Nc + col) = make_float2(v10, v11);
            }
        }
    }
}

// ---------------- Flash attention (fp32), ctx -> bf16 hi/lo -----------------
__global__ __launch_bounds__(256) void attn_kernel(const float* __restrict__ qkv,
                                                   __nv_bfloat16* __restrict__ ctx_hi,
                                                   __nv_bfloat16* __restrict__ ctx_lo)
{
    int b  = blockIdx.z, h = blockIdx.y, qt = blockIdx.x;
    int c  = g_counts[b];
    int s  = g_starts[b];
    int q0 = qt << 6;
    if (q0 >= c) return;

    int tid = threadIdx.x;
    int tx = tid & 15, ty = tid >> 4;

    __shared__ float Qt[HD][68];
    __shared__ float Kt[HD][68];
    __shared__ float Vs[64][34];
    __shared__ float Ps[64][68];

    const float scale = 0.17677669529663687f;

#pragma unroll
    for (int l = 0; l < 8; l++) {
        int e = tid + (l << 8);
        int row = e >> 5, d = e & 31;
        float v = (q0 + row < c)
            ? qkv[(size_t)(s + q0 + row) * (3 * H) + h * HD + d] * scale : 0.f;
        Qt[d][row] = v;
    }

    float m[4], lsum[4], o0[4], o1[4];
#pragma unroll
    for (int i = 0; i < 4; i++) { m[i] = -1e30f; lsum[i] = 0.f; o0[i] = 0.f; o1[i] = 0.f; }

    for (int k0 = 0; k0 < c; k0 += 64) {
        __syncthreads();
#pragma unroll
        for (int l = 0; l < 8; l++) {
            int e = tid + (l << 8);
            int row = e >> 5, d = e & 31;
            bool ok = (k0 + row < c);
            size_t base = (size_t)(s + k0 + row) * (3 * H) + h * HD + d;
            Kt[d][row] = ok ? qkv[base + H]     : 0.f;
            Vs[row][d] = ok ? qkv[base + 2 * H] : 0.f;
        }
        __syncthreads();

        float sc[4][4];
#pragma unroll
        for (int i = 0; i < 4; i++) { sc[i][0] = sc[i][1] = sc[i][2] = sc[i][3] = 0.f; }
#pragma unroll
        for (int d = 0; d < HD; d++) {
            float4 qa = *(const float4*)&Qt[d][ty * 4];
            float4 kb = *(const float4*)&Kt[d][tx * 4];
            float qv[4] = {qa.x, qa.y, qa.z, qa.w};
            float kv[4] = {kb.x, kb.y, kb.z, kb.w};
#pragma unroll
            for (int i = 0; i < 4; i++)
#pragma unroll
                for (int j = 0; j < 4; j++)
                    sc[i][j] = fmaf(qv[i], kv[j], sc[i][j]);
        }
        int kvalid = c - k0;
#pragma unroll
        for (int j = 0; j < 4; j++)
            if (tx * 4 + j >= kvalid) {
#pragma unroll
                for (int i = 0; i < 4; i++) sc[i][j] = -1e30f;
            }

#pragma unroll
        for (int i = 0; i < 4; i++) {
            float mx = fmaxf(fmaxf(sc[i][0], sc[i][1]), fmaxf(sc[i][2], sc[i][3]));
            mx = fmaxf(mx, __shfl_xor_sync(0xffffffffu, mx, 1));
            mx = fmaxf(mx, __shfl_xor_sync(0xffffffffu, mx, 2));
            mx = fmaxf(mx, __shfl_xor_sync(0xffffffffu, mx, 4));
            mx = fmaxf(mx, __shfl_xor_sync(0xffffffffu, mx, 8));
            float mnew  = fmaxf(m[i], mx);
            float alpha = __expf(m[i] - mnew);
            float ps = 0.f;
#pragma unroll
            for (int j = 0; j < 4; j++) {
                float p = __expf(sc[i][j] - mnew);
                Ps[ty * 4 + i][tx * 4 + j] = p;
                ps += p;
            }
            ps += __shfl_xor_sync(0xffffffffu, ps, 1);
            ps += __shfl_xor_sync(0xffffffffu, ps, 2);
            ps += __shfl_xor_sync(0xffffffffu, ps, 4);
            ps += __shfl_xor_sync(0xffffffffu, ps, 8);
            lsum[i] = lsum[i] * alpha + ps;
            o0[i] *= alpha; o1[i] *= alpha;
            m[i] = mnew;
        }
        __syncwarp();

#pragma unroll 4
        for (int kk = 0; kk < 64; kk++) {
            float2 v2 = *(const float2*)&Vs[kk][tx * 2];
#pragma unroll
            for (int i = 0; i < 4; i++) {
                float p = Ps[ty * 4 + i][kk];
                o0[i] = fmaf(p, v2.x, o0[i]);
                o1[i] = fmaf(p, v2.y, o1[i]);
            }
        }
    }

#pragma unroll
    for (int i = 0; i < 4; i++) {
        int q = q0 + ty * 4 + i;
        if (q < c) {
            float inv = 1.f / lsum[i];
            size_t base = (size_t)(s + q) * H + h * HD + tx * 2;
            split_store(o0[i] * inv, ctx_hi, ctx_lo, base);
            split_store(o1[i] * inv, ctx_hi, ctx_lo, base + 1);
        }
    }
}

// ======================= launch =============================================
extern "C" void kernel_launch(void* const* d_in, const int* in_sizes, int n_in,
                              void* d_out, int out_size)
{
    const float* x     = (const float*)d_in[0];
    const int*   batch = (const int*)d_in[1];
    int base = (n_in >= 15 && in_sizes[2] == 1) ? 3 : 2;
    const float* n1w = (const float*)d_in[base + 0];
    const float* n1b = (const float*)d_in[base + 1];
    const float* iw  = (const float*)d_in[base + 2];
    const float* ib  = (const float*)d_in[base + 3];
    const float* ow  = (const float*)d_in[base + 4];
    const float* ob  = (const float*)d_in[base + 5];
    const float* n2w = (const float*)d_in[base + 6];
    const float* n2b = (const float*)d_in[base + 7];
    const float* w1  = (const float*)d_in[base + 8];
    const float* b1  = (const float*)d_in[base + 9];
    const float* w2  = (const float*)d_in[base + 10];
    const float* b2  = (const float*)d_in[base + 11];
    float* out = (float*)d_out;

    cudaFuncSetAttribute(hgemm_kernel<0>, cudaFuncAttributeMaxDynamicSharedMemorySize, GEMM_SMEM);
    cudaFuncSetAttribute(hgemm_kernel<1>, cudaFuncAttributeMaxDynamicSharedMemorySize, GEMM_SMEM);
    cudaFuncSetAttribute(hgemm_kernel<2>, cudaFuncAttributeMaxDynamicSharedMemorySize, GEMM_SMEM);

    __nv_bfloat16 *p_xnh, *p_xnl, *p_ctxh, *p_ctxl, *p_xn2h, *p_xn2l, *p_hidh, *p_hidl;
    __nv_bfloat16 *p_wqh, *p_wql, *p_woh, *p_wol, *p_w1h, *p_w1l, *p_w2h, *p_w2l;
    float *p_qkv, *p_xmid;
    cudaGetSymbolAddress((void**)&p_xnh,  g_xn_hi);   cudaGetSymbolAddress((void**)&p_xnl,  g_xn_lo);
    cudaGetSymbolAddress((void**)&p_qkv,  g_qkv);
    cudaGetSymbolAddress((void**)&p_ctxh, g_ctx_hi);  cudaGetSymbolAddress((void**)&p_ctxl, g_ctx_lo);
    cudaGetSymbolAddress((void**)&p_xmid, g_xmid);
    cudaGetSymbolAddress((void**)&p_xn2h, g_xn2_hi);  cudaGetSymbolAddress((void**)&p_xn2l, g_xn2_lo);
    cudaGetSymbolAddress((void**)&p_hidh, g_hid_hi);  cudaGetSymbolAddress((void**)&p_hidl, g_hid_lo);
    cudaGetSymbolAddress((void**)&p_wqh,  g_wqkv_hi); cudaGetSymbolAddress((void**)&p_wql,  g_wqkv_lo);
    cudaGetSymbolAddress((void**)&p_woh,  g_wout_hi); cudaGetSymbolAddress((void**)&p_wol,  g_wout_lo);
    cudaGetSymbolAddress((void**)&p_w1h,  g_w1_hi);   cudaGetSymbolAddress((void**)&p_w1l,  g_w1_lo);
    cudaGetSymbolAddress((void**)&p_w2h,  g_w2_hi);   cudaGetSymbolAddress((void**)&p_w2l,  g_w2_lo);

    count_kernel<<<1, 256>>>(batch);
    convert_kernel<<<(3 * H * H + 255) / 256, 256>>>(iw, p_wqh, p_wql, 3 * H * H);
    convert_kernel<<<(H * H + 255) / 256, 256>>>(ow, p_woh, p_wol, H * H);
    convert_kernel<<<(4 * H * H + 255) / 256, 256>>>(w1, p_w1h, p_w1l, 4 * H * H);
    convert_kernel<<<(4 * H * H + 255) / 256, 256>>>(w2, p_w2h, p_w2l, 4 * H * H);

    graphnorm_kernel<<<BG, H>>>(x, n1w, n1b, p_xnh, p_xnl);

    hgemm_kernel<0><<<dim3(3 * H / 128, NN / 128), 256, GEMM_SMEM>>>(
        p_xnh, p_xnl, p_wqh, p_wql, ib, nullptr, p_qkv, nullptr, nullptr, 3 * H, H);

    attn_kernel<<<dim3(8, NHEADS, BG), 256>>>(p_qkv, p_ctxh, p_ctxl);

    hgemm_kernel<1><<<dim3(H / 128, NN / 128), 256, GEMM_SMEM>>>(
        p_ctxh, p_ctxl, p_woh, p_wol, ob, x, p_xmid, nullptr, nullptr, H, H);

    graphnorm_kernel<<<BG, H>>>(p_xmid, n2w, n2b, p_xn2h, p_xn2l);

    hgemm_kernel<2><<<dim3(4 * H / 128, NN / 128), 256, GEMM_SMEM>>>(
        p_xn2h, p_xn2l, p_w1h, p_w1l, b1, nullptr, nullptr, p_hidh, p_hidl, 4 * H, H);

    hgemm_kernel<1><<<dim3(H / 128, NN / 128), 256, GEMM_SMEM>>>(
        p_hidh, p_hidl, p_w2h, p_w2l, b2, p_xmid, out, nullptr, nullptr, H, 4 * H);
}

// round 5
// speedup vs baseline: 1.8496x; 1.2632x over previous
#include <cuda_runtime.h>
#include <cuda_bf16.h>
#include <math.h>
#include <stdint.h>

#define NN      16384
#define BG      64
#define H       256
#define NHEADS  8
#define HD      32

// ======================= scratch (device globals) ===========================
__device__ __nv_bfloat16 g_xn_hi[NN * H],      g_xn_lo[NN * H];
__device__ __nv_bfloat16 g_qkv_hi[NN * 3 * H], g_qkv_lo[NN * 3 * H];
__device__ __nv_bfloat16 g_ctx_hi[NN * H],     g_ctx_lo[NN * H];
__device__ float         g_xmid[NN * H];
__device__ __nv_bfloat16 g_xn2_hi[NN * H],     g_xn2_lo[NN * H];
__device__ __nv_bfloat16 g_hid_hi[NN * 4 * H], g_hid_lo[NN * 4 * H];
__device__ __nv_bfloat16 g_wqkv_hi[3 * H * H], g_wqkv_lo[3 * H * H];
__device__ __nv_bfloat16 g_wout_hi[H * H],     g_wout_lo[H * H];
__device__ __nv_bfloat16 g_w1_hi[4 * H * H],   g_w1_lo[4 * H * H];
__device__ __nv_bfloat16 g_w2_hi[H * 4 * H],   g_w2_lo[H * 4 * H];
__device__ int g_counts[BG];
__device__ int g_starts[BG];

__device__ __forceinline__ void split_store(float v, __nv_bfloat16* hi, __nv_bfloat16* lo, size_t idx) {
    __nv_bfloat16 h = __float2bfloat16(v);
    hi[idx] = h;
    lo[idx] = __float2bfloat16(v - __bfloat162float(h));
}

__device__ __forceinline__ uint32_t smem_u32(const void* p) {
    uint32_t a;
    asm("{ .reg .u64 t; cvta.to.shared.u64 t, %1; cvt.u32.u64 %0, t; }" : "=r"(a) : "l"(p));
    return a;
}
#define CP_ASYNC16(dst, src) \
    asm volatile("cp.async.cg.shared.global [%0], [%1], 16;" :: "r"(dst), "l"(src))
#define CP_ASYNC16Z(dst, src, vbytes) \
    asm volatile("cp.async.cg.shared.global [%0], [%1], 16, %2;" :: "r"(dst), "l"(src), "r"(vbytes))
#define CP_COMMIT() asm volatile("cp.async.commit_group;" ::: "memory")
#define CP_WAIT(n)  asm volatile("cp.async.wait_group %0;" :: "n"(n) : "memory")

#define LDSM4(r, addr) \
    asm volatile("ldmatrix.sync.aligned.m8n8.x4.shared.b16 {%0,%1,%2,%3}, [%4];" \
        : "=r"((r)[0]), "=r"((r)[1]), "=r"((r)[2]), "=r"((r)[3]) : "r"(addr))
#define LDSM4T(r, addr) \
    asm volatile("ldmatrix.sync.aligned.m8n8.x4.trans.shared.b16 {%0,%1,%2,%3}, [%4];" \
        : "=r"((r)[0]), "=r"((r)[1]), "=r"((r)[2]), "=r"((r)[3]) : "r"(addr))

__device__ __forceinline__ void mma16816(float* c, const uint32_t* a, const uint32_t* b) {
    asm volatile("mma.sync.aligned.m16n8k16.row.col.f32.bf16.bf16.f32 "
        "{%0,%1,%2,%3}, {%4,%5,%6,%7}, {%8,%9}, {%0,%1,%2,%3};"
        : "+f"(c[0]), "+f"(c[1]), "+f"(c[2]), "+f"(c[3])
        : "r"(a[0]), "r"(a[1]), "r"(a[2]), "r"(a[3]), "r"(b[0]), "r"(b[1]));
}

__device__ __forceinline__ void split_pack(float x, float y, uint32_t& hi, uint32_t& lo) {
    __nv_bfloat16 hx = __float2bfloat16(x), hy = __float2bfloat16(y);
    __nv_bfloat162 h; h.x = hx; h.y = hy;
    __nv_bfloat162 l;
    l.x = __float2bfloat16(x - __bfloat162float(hx));
    l.y = __float2bfloat16(y - __bfloat162float(hy));
    hi = *(uint32_t*)&h; lo = *(uint32_t*)&l;
}

// ---------------- counts / starts ------------------------------------------
__global__ void count_kernel(const int* __restrict__ batch)
{
    __shared__ int s[BG];
    int t = threadIdx.x;
    if (t < BG) s[t] = 0;
    __syncthreads();
    for (int i = t; i < NN; i += blockDim.x) atomicAdd(&s[batch[i]], 1);
    __syncthreads();
    if (t == 0) {
        int acc = 0;
        for (int b = 0; b < BG; b++) { g_starts[b] = acc; g_counts[b] = s[b]; acc += s[b]; }
    }
}

// ---------------- weight fp32 -> bf16 hi/lo ---------------------------------
__global__ void convert_kernel(const float* __restrict__ src,
                               __nv_bfloat16* __restrict__ hi,
                               __nv_bfloat16* __restrict__ lo, int n)
{
    int i = blockIdx.x * blockDim.x + threadIdx.x;
    if (i < n) split_store(src[i], hi, lo, i);
}

// ---------------- GraphNorm (8-way row-parallel) ----------------------------
__global__ void graphnorm_kernel(const float* __restrict__ in,
                                 const float* __restrict__ w,
                                 const float* __restrict__ bias,
                                 __nv_bfloat16* __restrict__ oh,
                                 __nv_bfloat16* __restrict__ ol)
{
    int b = blockIdx.x;
    int c = g_counts[b];
    long s = g_starts[b];
    if (c == 0) return;
    int t = threadIdx.x;
    int f = blockIdx.y * 32 + (t & 31);
    int rl = t >> 5;                        // 0..7

    __shared__ float ssum[8][33], ssq[8][33], smean[32], sinv[32];

    float sum = 0.f, sq = 0.f;
    for (int i = rl; i < c; i += 8) {
        float v = in[(s + i) * H + f];
        sum += v; sq += v * v;
    }
    ssum[rl][t & 31] = sum; ssq[rl][t & 31] = sq;
    __syncthreads();
    if (rl == 0) {
        float ts = 0.f, tq = 0.f;
        #pragma unroll
        for (int k = 0; k < 8; k++) { ts += ssum[k][t & 31]; tq += ssq[k][t & 31]; }
        float cf = (float)c;
        float mean = ts / cf;
        float var = fmaxf((tq - ts * ts / cf) / fmaxf(cf - 1.f, 1.f), 0.f);
        smean[t & 31] = mean;
        sinv[t & 31] = 1.f / (sqrtf(var) + 1e-5f);
    }
    __syncthreads();
    float mean = smean[t & 31], inv = sinv[t & 31];
    float ww = w[f], bb = bias[f];
    for (int i = rl; i < c; i += 8) {
        float v = ww * ((in[(s + i) * H + f] - mean) * inv) + bb;
        split_store(v, oh, ol, (s + i) * H + f);
    }
}

// ======================= HMMA GEMM (bf16x3, ldmatrix, 4-stage) ==============
#define SROW   80
#define ARR_SZ (128 * SROW)        // 10240
#define STG_SZ (4 * ARR_SZ)        // 40960
#define GEMM_SMEM (4 * STG_SZ)     // 163840

template<int EPI>   // 1: bias+res->f32   2: gelu(bias)->bf16 hi/lo   3: bias->bf16 hi/lo
__global__ __launch_bounds__(256, 1) void hgemm_kernel(
    const __nv_bfloat16* __restrict__ Ah, const __nv_bfloat16* __restrict__ Al,
    const __nv_bfloat16* __restrict__ Bh, const __nv_bfloat16* __restrict__ Bl,
    const float* __restrict__ bias, const float* __restrict__ res,
    float* __restrict__ Cf, __nv_bfloat16* __restrict__ Ch, __nv_bfloat16* __restrict__ Cl,
    int Nc, int K)
{
    extern __shared__ char sm[];
    const int tid  = threadIdx.x;
    const int wid  = tid >> 5, lane = tid & 31;
    const int quad = lane >> 2, pair = lane & 3;
    const int m0 = blockIdx.y << 7, n0 = blockIdx.x << 7;
    const int wm = (wid & 1) << 6;
    const int wn = (wid >> 1) << 5;
    const uint32_t smb = smem_u32(sm);

    // ldmatrix per-lane offsets (SROW=80 -> conflict-free, 16B aligned)
    const int offA = ((lane & 7) + ((lane >> 3) & 1) * 8) * SROW + ((lane >> 4) & 1) * 16;
    const int offB = (((lane >> 4) & 1) * 8 + (lane & 7)) * SROW + ((lane >> 3) & 1) * 16;

    const char* gsrc[4] = { (const char*)Ah, (const char*)Al, (const char*)Bh, (const char*)Bl };

    float acc[4][4][4];
    #pragma unroll
    for (int a = 0; a < 4; a++)
        #pragma unroll
        for (int b = 0; b < 4; b++)
            #pragma unroll
            for (int r = 0; r < 4; r++) acc[a][b][r] = 0.f;

    const int nchunk = K >> 5;

    auto load_chunk = [&](int stage, int k0) {
        uint32_t sb = smb + stage * STG_SZ;
        #pragma unroll
        for (int t = 0; t < 8; t++) {
            int task = tid + (t << 8);
            int arr  = task >> 9;
            int idx  = task & 511;
            int row  = idx >> 2, ch = idx & 3;
            int r0   = (arr < 2) ? m0 : n0;
            const char* src = gsrc[arr] + ((size_t)(r0 + row) * K + k0 + ch * 8) * 2;
            uint32_t dst = sb + arr * ARR_SZ + row * SROW + ch * 16;
            CP_ASYNC16(dst, src);
        }
        CP_COMMIT();
    };

    load_chunk(0, 0);
    load_chunk(1, 32);
    for (int c = 0; c < nchunk; c++) {
        if (c + 2 < nchunk) load_chunk((c + 2) & 3, (c + 2) << 5);
        else                CP_COMMIT();
        CP_WAIT(2);
        __syncthreads();

        const int stg = (c & 3) * STG_SZ;
        #pragma unroll
        for (int ks = 0; ks < 2; ks++) {
            const int kb = ks * 32;
            uint32_t afh[4][4], afl[4][4], bfh[2][4], bfl[2][4];
            #pragma unroll
            for (int mt = 0; mt < 4; mt++) {
                uint32_t a = smb + stg + (wm + mt * 16) * SROW + kb + offA;
                LDSM4(afh[mt], a);
                LDSM4(afl[mt], a + ARR_SZ);
            }
            #pragma unroll
            for (int jp = 0; jp < 2; jp++) {
                uint32_t a = smb + stg + 2 * ARR_SZ + (wn + jp * 16) * SROW + kb + offB;
                LDSM4(bfh[jp], a);
                LDSM4(bfl[jp], a + ARR_SZ);
            }
            #pragma unroll
            for (int mt = 0; mt < 4; mt++)
                #pragma unroll
                for (int nt = 0; nt < 4; nt++) {
                    const uint32_t* bh = &bfh[nt >> 1][(nt & 1) * 2];
                    const uint32_t* bl = &bfl[nt >> 1][(nt & 1) * 2];
                    mma16816(acc[mt][nt], afh[mt], bh);
                    mma16816(acc[mt][nt], afl[mt], bh);
                    mma16816(acc[mt][nt], afh[mt], bl);
                }
        }
    }

    // ---- epilogue ----
    #pragma unroll
    for (int mt = 0; mt < 4; mt++) {
        int row0 = m0 + wm + mt * 16 + quad;
        int row1 = row0 + 8;
        #pragma unroll
        for (int nt = 0; nt < 4; nt++) {
            int col = n0 + wn + nt * 8 + pair * 2;
            float b0v = bias[col], b1v = bias[col + 1];
            float v00 = acc[mt][nt][0] + b0v, v01 = acc[mt][nt][1] + b1v;
            float v10 = acc[mt][nt][2] + b0v, v11 = acc[mt][nt][3] + b1v;
            if (EPI == 2) {
                v00 = 0.5f * v00 * (1.f + erff(v00 * 0.70710678118654752f));
                v01 = 0.5f * v01 * (1.f + erff(v01 * 0.70710678118654752f));
                v10 = 0.5f * v10 * (1.f + erff(v10 * 0.70710678118654752f));
                v11 = 0.5f * v11 * (1.f + erff(v11 * 0.70710678118654752f));
            }
            if (EPI == 2 || EPI == 3) {
                split_store(v00, Ch, Cl, (size_t)row0 * Nc + col);
                split_store(v01, Ch, Cl, (size_t)row0 * Nc + col + 1);
                split_store(v10, Ch, Cl, (size_t)row1 * Nc + col);
                split_store(v11, Ch, Cl, (size_t)row1 * Nc + col + 1);
            } else {
                v00 += res[(size_t)row0 * Nc + col];
                v01 += res[(size_t)row0 * Nc + col + 1];
                v10 += res[(size_t)row1 * Nc + col];
                v11 += res[(size_t)row1 * Nc + col + 1];
                *(float2*)(Cf + (size_t)row0 * Nc + col) = make_float2(v00, v01);
                *(float2*)(Cf + (size_t)row1 * Nc + col) = make_float2(v10, v11);
            }
        }
    }
}

// ================= tensor-core flash attention (bf16x3) =====================
// grid (8 qtiles, NHEADS, BG), 128 threads (4 warps, 16 q-rows each)
#define AQH 0
#define AQL 5120
#define AKH 10240
#define AKL 15360
#define AVH 20480
#define AVL 25600
#define ATT_SMEM 30720

__global__ __launch_bounds__(128) void attn_kernel(
    const __nv_bfloat16* __restrict__ qh_g, const __nv_bfloat16* __restrict__ ql_g,
    __nv_bfloat16* __restrict__ ctx_hi, __nv_bfloat16* __restrict__ ctx_lo)
{
    int b  = blockIdx.z, h = blockIdx.y, qt = blockIdx.x;
    int cc = g_counts[b];
    int s  = g_starts[b];
    int q0 = qt << 6;
    if (q0 >= cc) return;

    __shared__ alignas(128) char sm[ATT_SMEM];
    const uint32_t smb = smem_u32(sm);
    const int tid = threadIdx.x, w = tid >> 5, l = tid & 31;

    const int offA = ((l & 7) + ((l >> 3) & 1) * 8) * SROW + ((l >> 4) & 1) * 16;
    const int offB = (((l >> 4) & 1) * 8 + (l & 7)) * SROW + ((l >> 3) & 1) * 16;
    const int offT = offA;   // trans-load lane offset (same formula)

    // ---- issue Q tile (64 x 32, hi/lo) ----
    {
        #pragma unroll
        for (int t = 0; t < 4; t++) {
            int task = tid + (t << 7);          // 0..511
            int arr = task >> 8, idx = task & 255;
            int row = idx >> 2, seg = idx & 3;
            const __nv_bfloat16* src = (arr ? ql_g : qh_g)
                + (size_t)(s + q0 + row) * (3 * H) + h * HD + seg * 8;
            uint32_t dst = smb + arr * 5120 + row * SROW + seg * 16;
            CP_ASYNC16Z(dst, src, (q0 + row < cc) ? 16u : 0u);
        }
        CP_COMMIT();
    }
    // ---- issue K/V tile 0 ----
    auto issue_kv = [&](int k0) {
        #pragma unroll
        for (int t = 0; t < 8; t++) {
            int task = tid + (t << 7);          // 0..1023
            int arr = task >> 8, idx = task & 255;   // 0 Kh, 1 Kl, 2 Vh, 3 Vl
            int row = idx >> 2, seg = idx & 3;
            const __nv_bfloat16* base = (arr & 1) ? ql_g : qh_g;
            int coloff = h * HD + ((arr >> 1) + 1) * H;   // K at +H, V at +2H
            const __nv_bfloat16* src = base + (size_t)(s + k0 + row) * (3 * H) + coloff + seg * 8;
            uint32_t dst = smb + AKH + arr * 5120 + row * SROW + seg * 16;
            CP_ASYNC16Z(dst, src, (k0 + row < cc) ? 16u : 0u);
        }
        CP_COMMIT();
    };
    issue_kv(0);
    CP_WAIT(0);
    __syncthreads();

    // ---- Q fragments (registers, whole kernel) ----
    uint32_t qfh[2][4], qfl[2][4];
    #pragma unroll
    for (int kc = 0; kc < 2; kc++) {
        uint32_t a = smb + AQH + (w * 16) * SROW + kc * 32 + offA;
        LDSM4(qfh[kc], a);
        LDSM4(qfl[kc], a + 5120);
    }

    const float scale = 0.17677669529663687f;
    float m0 = -1e30f, m1 = -1e30f, ls0 = 0.f, ls1 = 0.f;
    float o[4][4];
    #pragma unroll
    for (int dt = 0; dt < 4; dt++)
        #pragma unroll
        for (int r = 0; r < 4; r++) o[dt][r] = 0.f;

    for (int k0 = 0; k0 < cc; k0 += 64) {
        // ---- S = Q K^T (bf16x3) ----
        float sc[8][4];
        #pragma unroll
        for (int j = 0; j < 8; j++)
            #pragma unroll
            for (int r = 0; r < 4; r++) sc[j][r] = 0.f;

        #pragma unroll
        for (int jp = 0; jp < 4; jp++) {
            #pragma unroll
            for (int kc = 0; kc < 2; kc++) {
                uint32_t kh[4], kl[4];
                uint32_t a = smb + AKH + (jp * 16) * SROW + kc * 32 + offB;
                LDSM4(kh, a);
                LDSM4(kl, a + 5120);
                mma16816(sc[2 * jp],     qfh[kc], kh);
                mma16816(sc[2 * jp],     qfl[kc], kh);
                mma16816(sc[2 * jp],     qfh[kc], kl);
                mma16816(sc[2 * jp + 1], qfh[kc], kh + 2);
                mma16816(sc[2 * jp + 1], qfl[kc], kh + 2);
                mma16816(sc[2 * jp + 1], qfh[kc], kl + 2);
            }
        }
        // ---- scale + mask ----
        int colb = k0 + 2 * (l & 3);
        #pragma unroll
        for (int j = 0; j < 8; j++) {
            int c0 = colb + j * 8, c1 = c0 + 1;
            sc[j][0] = (c0 < cc) ? sc[j][0] * scale : -1e9f;
            sc[j][1] = (c1 < cc) ? sc[j][1] * scale : -1e9f;
            sc[j][2] = (c0 < cc) ? sc[j][2] * scale : -1e9f;
            sc[j][3] = (c1 < cc) ? sc[j][3] * scale : -1e9f;
        }
        // ---- softmax update ----
        float mx0 = -1e30f, mx1 = -1e30f;
        #pragma unroll
        for (int j = 0; j < 8; j++) {
            mx0 = fmaxf(mx0, fmaxf(sc[j][0], sc[j][1]));
            mx1 = fmaxf(mx1, fmaxf(sc[j][2], sc[j][3]));
        }
        mx0 = fmaxf(mx0, __shfl_xor_sync(0xffffffffu, mx0, 1));
        mx0 = fmaxf(mx0, __shfl_xor_sync(0xffffffffu, mx0, 2));
        mx1 = fmaxf(mx1, __shfl_xor_sync(0xffffffffu, mx1, 1));
        mx1 = fmaxf(mx1, __shfl_xor_sync(0xffffffffu, mx1, 2));
        float nm0 = fmaxf(m0, mx0), nm1 = fmaxf(m1, mx1);
        float a0 = __expf(m0 - nm0), a1 = __expf(m1 - nm1);
        float ps0 = 0.f, ps1 = 0.f;
        #pragma unroll
        for (int j = 0; j < 8; j++) {
            sc[j][0] = __expf(sc[j][0] - nm0);
            sc[j][1] = __expf(sc[j][1] - nm0);
            sc[j][2] = __expf(sc[j][2] - nm1);
            sc[j][3] = __expf(sc[j][3] - nm1);
            ps0 += sc[j][0] + sc[j][1];
            ps1 += sc[j][2] + sc[j][3];
        }
        ls0 = ls0 * a0 + ps0;
        ls1 = ls1 * a1 + ps1;
        m0 = nm0; m1 = nm1;
        // ---- P fragments (bf16 hi/lo) ----
        uint32_t pah[4][4], pal[4][4];
        #pragma unroll
        for (int kc = 0; kc < 4; kc++) {
            int j = 2 * kc;
            split_pack(sc[j][0],     sc[j][1],     pah[kc][0], pal[kc][0]);
            split_pack(sc[j][2],     sc[j][3],     pah[kc][1], pal[kc][1]);
            split_pack(sc[j + 1][0], sc[j + 1][1], pah[kc][2], pal[kc][2]);
            split_pack(sc[j + 1][2], sc[j + 1][3], pah[kc][3], pal[kc][3]);
        }
        // ---- rescale O ----
        #pragma unroll
        for (int dt = 0; dt < 4; dt++) {
            o[dt][0] *= a0; o[dt][1] *= a0;
            o[dt][2] *= a1; o[dt][3] *= a1;
        }
        // ---- O += P V (bf16x3) ----
        #pragma unroll
        for (int kc = 0; kc < 4; kc++) {
            uint32_t vhA[4], vlA[4], vhB[4], vlB[4];
            uint32_t a = smb + AVH + (kc * 16) * SROW + offT;
            LDSM4T(vhA, a);
            LDSM4T(vhB, a + 32);
            LDSM4T(vlA, a + 5120);
            LDSM4T(vlB, a + 5120 + 32);
            mma16816(o[0], pah[kc], vhA);     mma16816(o[0], pal[kc], vhA);     mma16816(o[0], pah[kc], vlA);
            mma16816(o[1], pah[kc], vhA + 2); mma16816(o[1], pal[kc], vhA + 2); mma16816(o[1], pah[kc], vlA + 2);
            mma16816(o[2], pah[kc], vhB);     mma16816(o[2], pal[kc], vhB);     mma16816(o[2], pah[kc], vlB);
            mma16816(o[3], pah[kc], vhB + 2); mma16816(o[3], pal[kc], vhB + 2); mma16816(o[3], pah[kc], vlB + 2);
        }
        __syncthreads();
        if (k0 + 64 < cc) {
            issue_kv(k0 + 64);
            CP_WAIT(0);
        }
        __syncthreads();
    }

    // ---- finalize ----
    ls0 += __shfl_xor_sync(0xffffffffu, ls0, 1);
    ls0 += __shfl_xor_sync(0xffffffffu, ls0, 2);
    ls1 += __shfl_xor_sync(0xffffffffu, ls1, 1);
    ls1 += __shfl_xor_sync(0xffffffffu, ls1, 2);
    float inv0 = 1.f / ls0, inv1 = 1.f / ls1;
    int r0 = q0 + w * 16 + (l >> 2);
    int r1 = r0 + 8;
    #pragma unroll
    for (int dt = 0; dt < 4; dt++) {
        int d = h * HD + dt * 8 + 2 * (l & 3);
        if (r0 < cc) {
            uint32_t hi, lo;
            split_pack(o[dt][0] * inv0, o[dt][1] * inv0, hi, lo);
            *(uint32_t*)&ctx_hi[(size_t)(s + r0) * H + d] = hi;
            *(uint32_t*)&ctx_lo[(size_t)(s + r0) * H + d] = lo;
        }
        if (r1 < cc) {
            uint32_t hi, lo;
            split_pack(o[dt][2] * inv1, o[dt][3] * inv1, hi, lo);
            *(uint32_t*)&ctx_hi[(size_t)(s + r1) * H + d] = hi;
            *(uint32_t*)&ctx_lo[(size_t)(s + r1) * H + d] = lo;
        }
    }
}

// ======================= launch =============================================
extern "C" void kernel_launch(void* const* d_in, const int* in_sizes, int n_in,
                              void* d_out, int out_size)
{
    const float* x     = (const float*)d_in[0];
    const int*   batch = (const int*)d_in[1];
    int base = (n_in >= 15 && in_sizes[2] == 1) ? 3 : 2;
    const float* n1w = (const float*)d_in[base + 0];
    const float* n1b = (const float*)d_in[base + 1];
    const float* iw  = (const float*)d_in[base + 2];
    const float* ib  = (const float*)d_in[base + 3];
    const float* ow  = (const float*)d_in[base + 4];
    const float* ob  = (const float*)d_in[base + 5];
    const float* n2w = (const float*)d_in[base + 6];
    const float* n2b = (const float*)d_in[base + 7];
    const float* w1  = (const float*)d_in[base + 8];
    const float* b1  = (const float*)d_in[base + 9];
    const float* w2  = (const float*)d_in[base + 10];
    const float* b2  = (const float*)d_in[base + 11];
    float* out = (float*)d_out;

    cudaFuncSetAttribute(hgemm_kernel<1>, cudaFuncAttributeMaxDynamicSharedMemorySize, GEMM_SMEM);
    cudaFuncSetAttribute(hgemm_kernel<2>, cudaFuncAttributeMaxDynamicSharedMemorySize, GEMM_SMEM);
    cudaFuncSetAttribute(hgemm_kernel<3>, cudaFuncAttributeMaxDynamicSharedMemorySize, GEMM_SMEM);

    __nv_bfloat16 *p_xnh, *p_xnl, *p_qkvh, *p_qkvl, *p_ctxh, *p_ctxl, *p_xn2h, *p_xn2l, *p_hidh, *p_hidl;
    __nv_bfloat16 *p_wqh, *p_wql, *p_woh, *p_wol, *p_w1h, *p_w1l, *p_w2h, *p_w2l;
    float *p_xmid;
    cudaGetSymbolAddress((void**)&p_xnh,  g_xn_hi);   cudaGetSymbolAddress((void**)&p_xnl,  g_xn_lo);
    cudaGetSymbolAddress((void**)&p_qkvh, g_qkv_hi);  cudaGetSymbolAddress((void**)&p_qkvl, g_qkv_lo);
    cudaGetSymbolAddress((void**)&p_ctxh, g_ctx_hi);  cudaGetSymbolAddress((void**)&p_ctxl, g_ctx_lo);
    cudaGetSymbolAddress((void**)&p_xmid, g_xmid);
    cudaGetSymbolAddress((void**)&p_xn2h, g_xn2_hi);  cudaGetSymbolAddress((void**)&p_xn2l, g_xn2_lo);
    cudaGetSymbolAddress((void**)&p_hidh, g_hid_hi);  cudaGetSymbolAddress((void**)&p_hidl, g_hid_lo);
    cudaGetSymbolAddress((void**)&p_wqh,  g_wqkv_hi); cudaGetSymbolAddress((void**)&p_wql,  g_wqkv_lo);
    cudaGetSymbolAddress((void**)&p_woh,  g_wout_hi); cudaGetSymbolAddress((void**)&p_wol,  g_wout_lo);
    cudaGetSymbolAddress((void**)&p_w1h,  g_w1_hi);   cudaGetSymbolAddress((void**)&p_w1l,  g_w1_lo);
    cudaGetSymbolAddress((void**)&p_w2h,  g_w2_hi);   cudaGetSymbolAddress((void**)&p_w2l,  g_w2_lo);

    count_kernel<<<1, 256>>>(batch);
    convert_kernel<<<(3 * H * H + 255) / 256, 256>>>(iw, p_wqh, p_wql, 3 * H * H);
    convert_kernel<<<(H * H + 255) / 256, 256>>>(ow, p_woh, p_wol, H * H);
    convert_kernel<<<(4 * H * H + 255) / 256, 256>>>(w1, p_w1h, p_w1l, 4 * H * H);
    convert_kernel<<<(4 * H * H + 255) / 256, 256>>>(w2, p_w2h, p_w2l, 4 * H * H);

    graphnorm_kernel<<<dim3(BG, 8), 256>>>(x, n1w, n1b, p_xnh, p_xnl);

    hgemm_kernel<3><<<dim3(3 * H / 128, NN / 128), 256, GEMM_SMEM>>>(
        p_xnh, p_xnl, p_wqh, p_wql, ib, nullptr, nullptr, p_qkvh, p_qkvl, 3 * H, H);

    attn_kernel<<<dim3(8, NHEADS, BG), 128>>>(p_qkvh, p_qkvl, p_ctxh, p_ctxl);

    hgemm_kernel<1><<<dim3(H / 128, NN / 128), 256, GEMM_SMEM>>>(
        p_ctxh, p_ctxl, p_woh, p_wol, ob, x, p_xmid, nullptr, nullptr, H, H);

    graphnorm_kernel<<<dim3(BG, 8), 256>>>(p_xmid, n2w, n2b, p_xn2h, p_xn2l);

    hgemm_kernel<2><<<dim3(4 * H / 128, NN / 128), 256, GEMM_SMEM>>>(
        p_xn2h, p_xn2l, p_w1h, p_w1l, b1, nullptr, nullptr, p_hidh, p_hidl, 4 * H, H);

    hgemm_kernel<1><<<dim3(H / 128, NN / 128), 256, GEMM_SMEM>>>(
        p_hidh, p_hidl, p_w2h, p_w2l, b2, p_xmid, out, nullptr, nullptr, H, 4 * H);
}

// round 6
// speedup vs baseline: 2.3992x; 1.2971x over previous
#include <cuda_runtime.h>
#include <cuda_fp16.h>
#include <math.h>
#include <stdint.h>

#define NN      16384
#define BG      64
#define H       256
#define NHEADS  8
#define HD      32

// ======================= scratch (device globals) ===========================
__device__ __half g_xn_hi[NN * H],      g_xn_lo[NN * H];
__device__ __half g_qkv_hi[NN * 3 * H], g_qkv_lo[NN * 3 * H];
__device__ __half g_ctx_hi[NN * H],     g_ctx_lo[NN * H];
__device__ float  g_xmid[NN * H];
__device__ __half g_xn2_hi[NN * H],     g_xn2_lo[NN * H];
__device__ __half g_hid_hi[NN * 4 * H], g_hid_lo[NN * 4 * H];
__device__ __half g_wqkv[3 * H * H];
__device__ __half g_wout[H * H];
__device__ __half g_w1[4 * H * H];
__device__ __half g_w2[H * 4 * H];
__device__ int g_counts[BG];
__device__ int g_starts[BG];

__device__ __forceinline__ void split_store(float v, __half* hi, __half* lo, size_t idx) {
    __half h = __float2half(v);
    hi[idx] = h;
    lo[idx] = __float2half(v - __half2float(h));
}

__device__ __forceinline__ uint32_t smem_u32(const void* p) {
    uint32_t a;
    asm("{ .reg .u64 t; cvta.to.shared.u64 t, %1; cvt.u32.u64 %0, t; }" : "=r"(a) : "l"(p));
    return a;
}
#define CP_ASYNC16(dst, src) \
    asm volatile("cp.async.cg.shared.global [%0], [%1], 16;" :: "r"(dst), "l"(src))
#define CP_ASYNC16Z(dst, src, vbytes) \
    asm volatile("cp.async.cg.shared.global [%0], [%1], 16, %2;" :: "r"(dst), "l"(src), "r"(vbytes))
#define CP_COMMIT() asm volatile("cp.async.commit_group;" ::: "memory")
#define CP_WAIT(n)  asm volatile("cp.async.wait_group %0;" :: "n"(n) : "memory")

#define LDSM4(r, addr) \
    asm volatile("ldmatrix.sync.aligned.m8n8.x4.shared.b16 {%0,%1,%2,%3}, [%4];" \
        : "=r"((r)[0]), "=r"((r)[1]), "=r"((r)[2]), "=r"((r)[3]) : "r"(addr))
#define LDSM4T(r, addr) \
    asm volatile("ldmatrix.sync.aligned.m8n8.x4.trans.shared.b16 {%0,%1,%2,%3}, [%4];" \
        : "=r"((r)[0]), "=r"((r)[1]), "=r"((r)[2]), "=r"((r)[3]) : "r"(addr))

__device__ __forceinline__ void mma16816(float* c, const uint32_t* a, const uint32_t* b) {
    asm volatile("mma.sync.aligned.m16n8k16.row.col.f32.f16.f16.f32 "
        "{%0,%1,%2,%3}, {%4,%5,%6,%7}, {%8,%9}, {%0,%1,%2,%3};"
        : "+f"(c[0]), "+f"(c[1]), "+f"(c[2]), "+f"(c[3])
        : "r"(a[0]), "r"(a[1]), "r"(a[2]), "r"(a[3]), "r"(b[0]), "r"(b[1]));
}

__device__ __forceinline__ void split_pack(float x, float y, uint32_t& hi, uint32_t& lo) {
    __half hx = __float2half(x), hy = __float2half(y);
    __half2 h; h.x = hx; h.y = hy;
    __half2 l;
    l.x = __float2half(x - __half2float(hx));
    l.y = __float2half(y - __half2float(hy));
    hi = *(uint32_t*)&h; lo = *(uint32_t*)&l;
}

// ---------------- counts / starts ------------------------------------------
__global__ void count_kernel(const int* __restrict__ batch)
{
    __shared__ int s[BG];
    int t = threadIdx.x;
    if (t < BG) s[t] = 0;
    __syncthreads();
    for (int i = t; i < NN; i += blockDim.x) atomicAdd(&s[batch[i]], 1);
    __syncthreads();
    if (t == 0) {
        int acc = 0;
        for (int b = 0; b < BG; b++) { g_starts[b] = acc; g_counts[b] = s[b]; acc += s[b]; }
    }
}

// ---------------- weight fp32 -> fp16 (hi only) -----------------------------
__global__ void convert_kernel(const float* __restrict__ src, __half* __restrict__ hi, int n)
{
    int i = blockIdx.x * blockDim.x + threadIdx.x;
    if (i < n) hi[i] = __float2half(src[i]);
}

// ---------------- GraphNorm (8-way row-parallel) ----------------------------
__global__ void graphnorm_kernel(const float* __restrict__ in,
                                 const float* __restrict__ w,
                                 const float* __restrict__ bias,
                                 __half* __restrict__ oh,
                                 __half* __restrict__ ol)
{
    int b = blockIdx.x;
    int c = g_counts[b];
    long s = g_starts[b];
    if (c == 0) return;
    int t = threadIdx.x;
    int f = blockIdx.y * 32 + (t & 31);
    int rl = t >> 5;

    __shared__ float ssum[8][33], ssq[8][33], smean[32], sinv[32];

    float sum = 0.f, sq = 0.f;
    for (int i = rl; i < c; i += 8) {
        float v = in[(s + i) * H + f];
        sum += v; sq += v * v;
    }
    ssum[rl][t & 31] = sum; ssq[rl][t & 31] = sq;
    __syncthreads();
    if (rl == 0) {
        float ts = 0.f, tq = 0.f;
        #pragma unroll
        for (int k = 0; k < 8; k++) { ts += ssum[k][t & 31]; tq += ssq[k][t & 31]; }
        float cf = (float)c;
        float mean = ts / cf;
        float var = fmaxf((tq - ts * ts / cf) / fmaxf(cf - 1.f, 1.f), 0.f);
        smean[t & 31] = mean;
        sinv[t & 31] = 1.f / (sqrtf(var) + 1e-5f);
    }
    __syncthreads();
    float mean = smean[t & 31], inv = sinv[t & 31];
    float ww = w[f], bb = bias[f];
    for (int i = rl; i < c; i += 8) {
        float v = ww * ((in[(s + i) * H + f] - mean) * inv) + bb;
        split_store(v, oh, ol, (s + i) * H + f);
    }
}

// ======================= HMMA GEMM (fp16x2, ldmatrix, 4-stage) ==============
// C = (Ah + Al) @ Bh^T + bias (...).  3 smem arrays/stage: Ah, Al, Bh.
#define SROW   80
#define ARR_SZ (128 * SROW)        // 10240
#define STG_SZ (3 * ARR_SZ)        // 30720
#define GEMM_SMEM (4 * STG_SZ)     // 122880

template<int EPI>   // 1: bias+res->f32   2: gelu(bias)->fp16 hi/lo   3: bias->fp16 hi/lo (lo only col<H)
__global__ __launch_bounds__(256, 1) void hgemm_kernel(
    const __half* __restrict__ Ah, const __half* __restrict__ Al,
    const __half* __restrict__ Bh,
    const float* __restrict__ bias, const float* __restrict__ res,
    float* __restrict__ Cf, __half* __restrict__ Ch, __half* __restrict__ Cl,
    int Nc, int K)
{
    extern __shared__ char sm[];
    const int tid  = threadIdx.x;
    const int wid  = tid >> 5, lane = tid & 31;
    const int quad = lane >> 2, pair = lane & 3;
    const int m0 = blockIdx.y << 7, n0 = blockIdx.x << 7;
    const int wm = (wid & 1) << 6;
    const int wn = (wid >> 1) << 5;
    const uint32_t smb = smem_u32(sm);

    const int offA = ((lane & 7) + ((lane >> 3) & 1) * 8) * SROW + ((lane >> 4) & 1) * 16;
    const int offB = (((lane >> 4) & 1) * 8 + (lane & 7)) * SROW + ((lane >> 3) & 1) * 16;

    const char* gsrc[3] = { (const char*)Ah, (const char*)Al, (const char*)Bh };

    float acc[4][4][4];
    #pragma unroll
    for (int a = 0; a < 4; a++)
        #pragma unroll
        for (int b = 0; b < 4; b++)
            #pragma unroll
            for (int r = 0; r < 4; r++) acc[a][b][r] = 0.f;

    const int nchunk = K >> 5;

    auto load_chunk = [&](int stage, int k0) {
        uint32_t sb = smb + stage * STG_SZ;
        #pragma unroll
        for (int t = 0; t < 6; t++) {
            int task = tid + (t << 8);          // 0..1535
            int arr  = task >> 9;
            int idx  = task & 511;
            int row  = idx >> 2, ch = idx & 3;
            int r0   = (arr < 2) ? m0 : n0;
            const char* src = gsrc[arr] + ((size_t)(r0 + row) * K + k0 + ch * 8) * 2;
            uint32_t dst = sb + arr * ARR_SZ + row * SROW + ch * 16;
            CP_ASYNC16(dst, src);
        }
        CP_COMMIT();
    };

    load_chunk(0, 0);
    load_chunk(1, 32);
    for (int c = 0; c < nchunk; c++) {
        if (c + 2 < nchunk) load_chunk((c + 2) & 3, (c + 2) << 5);
        else                CP_COMMIT();
        CP_WAIT(2);
        __syncthreads();

        const int stg = (c & 3) * STG_SZ;
        #pragma unroll
        for (int ks = 0; ks < 2; ks++) {
            const int kb = ks * 32;
            uint32_t afh[4][4], afl[4][4], bfh[2][4];
            #pragma unroll
            for (int mt = 0; mt < 4; mt++) {
                uint32_t a = smb + stg + (wm + mt * 16) * SROW + kb + offA;
                LDSM4(afh[mt], a);
                LDSM4(afl[mt], a + ARR_SZ);
            }
            #pragma unroll
            for (int jp = 0; jp < 2; jp++) {
                uint32_t a = smb + stg + 2 * ARR_SZ + (wn + jp * 16) * SROW + kb + offB;
                LDSM4(bfh[jp], a);
            }
            #pragma unroll
            for (int mt = 0; mt < 4; mt++)
                #pragma unroll
                for (int nt = 0; nt < 4; nt++) {
                    const uint32_t* bh = &bfh[nt >> 1][(nt & 1) * 2];
                    mma16816(acc[mt][nt], afh[mt], bh);
                    mma16816(acc[mt][nt], afl[mt], bh);
                }
        }
    }

    // ---- epilogue ----
    #pragma unroll
    for (int mt = 0; mt < 4; mt++) {
        int row0 = m0 + wm + mt * 16 + quad;
        int row1 = row0 + 8;
        #pragma unroll
        for (int nt = 0; nt < 4; nt++) {
            int col = n0 + wn + nt * 8 + pair * 2;
            float b0v = bias[col], b1v = bias[col + 1];
            float v00 = acc[mt][nt][0] + b0v, v01 = acc[mt][nt][1] + b1v;
            float v10 = acc[mt][nt][2] + b0v, v11 = acc[mt][nt][3] + b1v;
            if (EPI == 2) {
                v00 = 0.5f * v00 * (1.f + erff(v00 * 0.70710678118654752f));
                v01 = 0.5f * v01 * (1.f + erff(v01 * 0.70710678118654752f));
                v10 = 0.5f * v10 * (1.f + erff(v10 * 0.70710678118654752f));
                v11 = 0.5f * v11 * (1.f + erff(v11 * 0.70710678118654752f));
            }
            if (EPI == 2 || EPI == 3) {
                bool wlo = (EPI == 2) || (col < H);   // QKV: lo needed only for Q block
                __half h00 = __float2half(v00), h01 = __float2half(v01);
                __half h10 = __float2half(v10), h11 = __float2half(v11);
                Ch[(size_t)row0 * Nc + col]     = h00;
                Ch[(size_t)row0 * Nc + col + 1] = h01;
                Ch[(size_t)row1 * Nc + col]     = h10;
                Ch[(size_t)row1 * Nc + col + 1] = h11;
                if (wlo) {
                    Cl[(size_t)row0 * Nc + col]     = __float2half(v00 - __half2float(h00));
                    Cl[(size_t)row0 * Nc + col + 1] = __float2half(v01 - __half2float(h01));
                    Cl[(size_t)row1 * Nc + col]     = __float2half(v10 - __half2float(h10));
                    Cl[(size_t)row1 * Nc + col + 1] = __float2half(v11 - __half2float(h11));
                }
            } else {
                v00 += res[(size_t)row0 * Nc + col];
                v01 += res[(size_t)row0 * Nc + col + 1];
                v10 += res[(size_t)row1 * Nc + col];
                v11 += res[(size_t)row1 * Nc + col + 1];
                *(float2*)(Cf + (size_t)row0 * Nc + col) = make_float2(v00, v01);
                *(float2*)(Cf + (size_t)row1 * Nc + col) = make_float2(v10, v11);
            }
        }
    }
}

// ================= tensor-core flash attention (fp16x2) =====================
// grid (8 qtiles, NHEADS, BG), 128 threads. Q hi/lo; K,V hi only; KV double-buffered.
#define AQH 0
#define AQL 5120
#define AKV 10240              // buf b at AKV + b*10240: [KH 5120][VH 5120]
#define ATT_SMEM 30720

__global__ __launch_bounds__(128) void attn_kernel(
    const __half* __restrict__ qh_g, const __half* __restrict__ ql_g,
    __half* __restrict__ ctx_hi, __half* __restrict__ ctx_lo)
{
    int b  = blockIdx.z, h = blockIdx.y, qt = blockIdx.x;
    int cc = g_counts[b];
    int s  = g_starts[b];
    int q0 = qt << 6;
    if (q0 >= cc) return;

    __shared__ alignas(128) char sm[ATT_SMEM];
    const uint32_t smb = smem_u32(sm);
    const int tid = threadIdx.x, w = tid >> 5, l = tid & 31;

    const int offA = ((l & 7) + ((l >> 3) & 1) * 8) * SROW + ((l >> 4) & 1) * 16;
    const int offB = (((l >> 4) & 1) * 8 + (l & 7)) * SROW + ((l >> 3) & 1) * 16;

    // ---- Q tile (64 x 32, hi/lo) ----
    {
        #pragma unroll
        for (int t = 0; t < 4; t++) {
            int task = tid + (t << 7);
            int arr = task >> 8, idx = task & 255;
            int row = idx >> 2, seg = idx & 3;
            const __half* src = (arr ? ql_g : qh_g)
                + (size_t)(s + q0 + row) * (3 * H) + h * HD + seg * 8;
            uint32_t dst = smb + arr * 5120 + row * SROW + seg * 16;
            CP_ASYNC16Z(dst, src, (q0 + row < cc) ? 16u : 0u);
        }
        CP_COMMIT();
    }
    auto issue_kv = [&](int k0, int buf) {
        #pragma unroll
        for (int t = 0; t < 4; t++) {
            int task = tid + (t << 7);               // 0..511
            int arr = task >> 8, idx = task & 255;   // 0 KH, 1 VH
            int row = idx >> 2, seg = idx & 3;
            int coloff = h * HD + (arr + 1) * H;     // K at +H, V at +2H
            const __half* src = qh_g + (size_t)(s + k0 + row) * (3 * H) + coloff + seg * 8;
            uint32_t dst = smb + AKV + buf * 10240 + arr * 5120 + row * SROW + seg * 16;
            CP_ASYNC16Z(dst, src, (k0 + row < cc) ? 16u : 0u);
        }
        CP_COMMIT();
    };
    issue_kv(0, 0);
    CP_WAIT(0);
    __syncthreads();

    uint32_t qfh[2][4], qfl[2][4];
    #pragma unroll
    for (int kc = 0; kc < 2; kc++) {
        uint32_t a = smb + AQH + (w * 16) * SROW + kc * 32 + offA;
        LDSM4(qfh[kc], a);
        LDSM4(qfl[kc], a + 5120);
    }

    const float scale = 0.17677669529663687f;
    float m0 = -1e30f, m1 = -1e30f, ls0 = 0.f, ls1 = 0.f;
    float o[4][4];
    #pragma unroll
    for (int dt = 0; dt < 4; dt++)
        #pragma unroll
        for (int r = 0; r < 4; r++) o[dt][r] = 0.f;

    int nch = (cc - 1) / 64 + 1;
    for (int ci = 0; ci * 64 < cc; ci++) {
        int k0 = ci * 64;
        uint32_t kvb = smb + AKV + (ci & 1) * 10240;
        // prefetch next chunk into other buffer (safe: other buf last read 2 chunks ago)
        if (ci + 1 < nch) issue_kv(k0 + 64, (ci + 1) & 1);

        // ---- S = Q K^T ----
        float sc[8][4];
        #pragma unroll
        for (int j = 0; j < 8; j++)
            #pragma unroll
            for (int r = 0; r < 4; r++) sc[j][r] = 0.f;

        #pragma unroll
        for (int jp = 0; jp < 4; jp++) {
            #pragma unroll
            for (int kc = 0; kc < 2; kc++) {
                uint32_t kh[4];
                LDSM4(kh, kvb + (jp * 16) * SROW + kc * 32 + offB);
                mma16816(sc[2 * jp],     qfh[kc], kh);
                mma16816(sc[2 * jp],     qfl[kc], kh);
                mma16816(sc[2 * jp + 1], qfh[kc], kh + 2);
                mma16816(sc[2 * jp + 1], qfl[kc], kh + 2);
            }
        }
        // ---- scale + mask ----
        int colb = k0 + 2 * (l & 3);
        #pragma unroll
        for (int j = 0; j < 8; j++) {
            int c0 = colb + j * 8, c1 = c0 + 1;
            sc[j][0] = (c0 < cc) ? sc[j][0] * scale : -1e9f;
            sc[j][1] = (c1 < cc) ? sc[j][1] * scale : -1e9f;
            sc[j][2] = (c0 < cc) ? sc[j][2] * scale : -1e9f;
            sc[j][3] = (c1 < cc) ? sc[j][3] * scale : -1e9f;
        }
        // ---- softmax update ----
        float mx0 = -1e30f, mx1 = -1e30f;
        #pragma unroll
        for (int j = 0; j < 8; j++) {
            mx0 = fmaxf(mx0, fmaxf(sc[j][0], sc[j][1]));
            mx1 = fmaxf(mx1, fmaxf(sc[j][2], sc[j][3]));
        }
        mx0 = fmaxf(mx0, __shfl_xor_sync(0xffffffffu, mx0, 1));
        mx0 = fmaxf(mx0, __shfl_xor_sync(0xffffffffu, mx0, 2));
        mx1 = fmaxf(mx1, __shfl_xor_sync(0xffffffffu, mx1, 1));
        mx1 = fmaxf(mx1, __shfl_xor_sync(0xffffffffu, mx1, 2));
        float nm0 = fmaxf(m0, mx0), nm1 = fmaxf(m1, mx1);
        float a0 = __expf(m0 - nm0), a1 = __expf(m1 - nm1);
        float ps0 = 0.f, ps1 = 0.f;
        #pragma unroll
        for (int j = 0; j < 8; j++) {
            sc[j][0] = __expf(sc[j][0] - nm0);
            sc[j][1] = __expf(sc[j][1] - nm0);
            sc[j][2] = __expf(sc[j][2] - nm1);
            sc[j][3] = __expf(sc[j][3] - nm1);
            ps0 += sc[j][0] + sc[j][1];
            ps1 += sc[j][2] + sc[j][3];
        }
        ls0 = ls0 * a0 + ps0;
        ls1 = ls1 * a1 + ps1;
        m0 = nm0; m1 = nm1;
        // ---- P fragments (fp16 hi/lo) ----
        uint32_t pah[4][4], pal[4][4];
        #pragma unroll
        for (int kc = 0; kc < 4; kc++) {
            int j = 2 * kc;
            split_pack(sc[j][0],     sc[j][1],     pah[kc][0], pal[kc][0]);
            split_pack(sc[j][2],     sc[j][3],     pah[kc][1], pal[kc][1]);
            split_pack(sc[j + 1][0], sc[j + 1][1], pah[kc][2], pal[kc][2]);
            split_pack(sc[j + 1][2], sc[j + 1][3], pah[kc][3], pal[kc][3]);
        }
        #pragma unroll
        for (int dt = 0; dt < 4; dt++) {
            o[dt][0] *= a0; o[dt][1] *= a0;
            o[dt][2] *= a1; o[dt][3] *= a1;
        }
        // ---- O += P V ----
        #pragma unroll
        for (int kc = 0; kc < 4; kc++) {
            uint32_t vhA[4], vhB[4];
            uint32_t a = kvb + 5120 + (kc * 16) * SROW + offA;
            LDSM4T(vhA, a);
            LDSM4T(vhB, a + 32);
            mma16816(o[0], pah[kc], vhA);     mma16816(o[0], pal[kc], vhA);
            mma16816(o[1], pah[kc], vhA + 2); mma16816(o[1], pal[kc], vhA + 2);
            mma16816(o[2], pah[kc], vhB);     mma16816(o[2], pal[kc], vhB);
            mma16816(o[3], pah[kc], vhB + 2); mma16816(o[3], pal[kc], vhB + 2);
        }
        if (ci + 1 < nch) CP_WAIT(0);
        __syncthreads();
    }

    // ---- finalize ----
    ls0 += __shfl_xor_sync(0xffffffffu, ls0, 1);
    ls0 += __shfl_xor_sync(0xffffffffu, ls0, 2);
    ls1 += __shfl_xor_sync(0xffffffffu, ls1, 1);
    ls1 += __shfl_xor_sync(0xffffffffu, ls1, 2);
    float inv0 = 1.f / ls0, inv1 = 1.f / ls1;
    int r0 = q0 + w * 16 + (l >> 2);
    int r1 = r0 + 8;
    #pragma unroll
    for (int dt = 0; dt < 4; dt++) {
        int d = h * HD + dt * 8 + 2 * (l & 3);
        if (r0 < cc) {
            uint32_t hi, lo;
            split_pack(o[dt][0] * inv0, o[dt][1] * inv0, hi, lo);
            *(uint32_t*)&ctx_hi[(size_t)(s + r0) * H + d] = hi;
            *(uint32_t*)&ctx_lo[(size_t)(s + r0) * H + d] = lo;
        }
        if (r1 < cc) {
            uint32_t hi, lo;
            split_pack(o[dt][2] * inv1, o[dt][3] * inv1, hi, lo);
            *(uint32_t*)&ctx_hi[(size_t)(s + r1) * H + d] = hi;
            *(uint32_t*)&ctx_lo[(size_t)(s + r1) * H + d] = lo;
        }
    }
}

// ======================= launch =============================================
extern "C" void kernel_launch(void* const* d_in, const int* in_sizes, int n_in,
                              void* d_out, int out_size)
{
    const float* x     = (const float*)d_in[0];
    const int*   batch = (const int*)d_in[1];
    int base = (n_in >= 15 && in_sizes[2] == 1) ? 3 : 2;
    const float* n1w = (const float*)d_in[base + 0];
    const float* n1b = (const float*)d_in[base + 1];
    const float* iw  = (const float*)d_in[base + 2];
    const float* ib  = (const float*)d_in[base + 3];
    const float* ow  = (const float*)d_in[base + 4];
    const float* ob  = (const float*)d_in[base + 5];
    const float* n2w = (const float*)d_in[base + 6];
    const float* n2b = (const float*)d_in[base + 7];
    const float* w1  = (const float*)d_in[base + 8];
    const float* b1  = (const float*)d_in[base + 9];
    const float* w2  = (const float*)d_in[base + 10];
    const float* b2  = (const float*)d_in[base + 11];
    float* out = (float*)d_out;

    cudaFuncSetAttribute(hgemm_kernel<1>, cudaFuncAttributeMaxDynamicSharedMemorySize, GEMM_SMEM);
    cudaFuncSetAttribute(hgemm_kernel<2>, cudaFuncAttributeMaxDynamicSharedMemorySize, GEMM_SMEM);
    cudaFuncSetAttribute(hgemm_kernel<3>, cudaFuncAttributeMaxDynamicSharedMemorySize, GEMM_SMEM);

    __half *p_xnh, *p_xnl, *p_qkvh, *p_qkvl, *p_ctxh, *p_ctxl, *p_xn2h, *p_xn2l, *p_hidh, *p_hidl;
    __half *p_wq, *p_wo, *p_w1, *p_w2;
    float *p_xmid;
    cudaGetSymbolAddress((void**)&p_xnh,  g_xn_hi);   cudaGetSymbolAddress((void**)&p_xnl,  g_xn_lo);
    cudaGetSymbolAddress((void**)&p_qkvh, g_qkv_hi);  cudaGetSymbolAddress((void**)&p_qkvl, g_qkv_lo);
    cudaGetSymbolAddress((void**)&p_ctxh, g_ctx_hi);  cudaGetSymbolAddress((void**)&p_ctxl, g_ctx_lo);
    cudaGetSymbolAddress((void**)&p_xmid, g_xmid);
    cudaGetSymbolAddress((void**)&p_xn2h, g_xn2_hi);  cudaGetSymbolAddress((void**)&p_xn2l, g_xn2_lo);
    cudaGetSymbolAddress((void**)&p_hidh, g_hid_hi);  cudaGetSymbolAddress((void**)&p_hidl, g_hid_lo);
    cudaGetSymbolAddress((void**)&p_wq,   g_wqkv);
    cudaGetSymbolAddress((void**)&p_wo,   g_wout);
    cudaGetSymbolAddress((void**)&p_w1,   g_w1);
    cudaGetSymbolAddress((void**)&p_w2,   g_w2);

    // order chosen so ncu (-s 5 -c 1) profiles the QKV hgemm (launch #5)
    count_kernel<<<1, 256>>>(batch);                                        // 0
    convert_kernel<<<(3 * H * H + 255) / 256, 256>>>(iw, p_wq, 3 * H * H);  // 1
    graphnorm_kernel<<<dim3(BG, 8), 256>>>(x, n1w, n1b, p_xnh, p_xnl);      // 2
    convert_kernel<<<(H * H + 255) / 256, 256>>>(ow, p_wo, H * H);          // 3
    convert_kernel<<<(4 * H * H + 255) / 256, 256>>>(w1, p_w1, 4 * H * H);  // 4

    hgemm_kernel<3><<<dim3(3 * H / 128, NN / 128), 256, GEMM_SMEM>>>(       // 5 <- profiled
        p_xnh, p_xnl, p_wq, ib, nullptr, nullptr, p_qkvh, p_qkvl, 3 * H, H);

    attn_kernel<<<dim3(8, NHEADS, BG), 128>>>(p_qkvh, p_qkvl, p_ctxh, p_ctxl);

    hgemm_kernel<1><<<dim3(H / 128, NN / 128), 256, GEMM_SMEM>>>(
        p_ctxh, p_ctxl, p_wo, ob, x, p_xmid, nullptr, nullptr, H, H);

    graphnorm_kernel<<<dim3(BG, 8), 256>>>(p_xmid, n2w, n2b, p_xn2h, p_xn2l);
    convert_kernel<<<(4 * H * H + 255) / 256, 256>>>(w2, p_w2, 4 * H * H);

    hgemm_kernel<2><<<dim3(4 * H / 128, NN / 128), 256, GEMM_SMEM>>>(
        p_xn2h, p_xn2l, p_w1, b1, nullptr, nullptr, p_hidh, p_hidl, 4 * H, H);

    hgemm_kernel<1><<<dim3(H / 128, NN / 128), 256, GEMM_SMEM>>>(
        p_hidh, p_hidl, p_w2, b2, p_xmid, out, nullptr, nullptr, H, 4 * H);
}

// round 7
// speedup vs baseline: 4.3028x; 1.7934x over previous
#include <cuda_runtime.h>
#include <cuda_fp16.h>
#include <math.h>
#include <stdint.h>

#define NN      16384
#define BG      64
#define H       256
#define NHEADS  8
#define HD      32

// ======================= scratch (device globals) ===========================
__device__ __half g_xn [NN * H];
__device__ __half g_qkv[NN * 3 * H];
__device__ __half g_ctx[NN * H];
__device__ float  g_xmid[NN * H];
__device__ __half g_xn2[NN * H];
__device__ __half g_hid[NN * 4 * H];
__device__ __half g_wqkv[3 * H * H];
__device__ __half g_wout[H * H];
__device__ __half g_w1[4 * H * H];
__device__ __half g_w2[H * 4 * H];
__device__ int g_counts[BG];
__device__ int g_starts[BG];

__device__ __forceinline__ uint32_t smem_u32(const void* p) {
    uint32_t a;
    asm("{ .reg .u64 t; cvta.to.shared.u64 t, %1; cvt.u32.u64 %0, t; }" : "=r"(a) : "l"(p));
    return a;
}
#define CP_ASYNC16(dst, src) \
    asm volatile("cp.async.cg.shared.global [%0], [%1], 16;" :: "r"(dst), "l"(src))
#define CP_ASYNC16Z(dst, src, vbytes) \
    asm volatile("cp.async.cg.shared.global [%0], [%1], 16, %2;" :: "r"(dst), "l"(src), "r"(vbytes))
#define CP_COMMIT() asm volatile("cp.async.commit_group;" ::: "memory")
#define CP_WAIT(n)  asm volatile("cp.async.wait_group %0;" :: "n"(n) : "memory")

#define LDSM4(r, addr) \
    asm volatile("ldmatrix.sync.aligned.m8n8.x4.shared.b16 {%0,%1,%2,%3}, [%4];" \
        : "=r"((r)[0]), "=r"((r)[1]), "=r"((r)[2]), "=r"((r)[3]) : "r"(addr))
#define LDSM4T(r, addr) \
    asm volatile("ldmatrix.sync.aligned.m8n8.x4.trans.shared.b16 {%0,%1,%2,%3}, [%4];" \
        : "=r"((r)[0]), "=r"((r)[1]), "=r"((r)[2]), "=r"((r)[3]) : "r"(addr))

__device__ __forceinline__ void mma16816(float* c, const uint32_t* a, const uint32_t* b) {
    asm volatile("mma.sync.aligned.m16n8k16.row.col.f32.f16.f16.f32 "
        "{%0,%1,%2,%3}, {%4,%5,%6,%7}, {%8,%9}, {%0,%1,%2,%3};"
        : "+f"(c[0]), "+f"(c[1]), "+f"(c[2]), "+f"(c[3])
        : "r"(a[0]), "r"(a[1]), "r"(a[2]), "r"(a[3]), "r"(b[0]), "r"(b[1]));
}

__device__ __forceinline__ uint32_t pack2(float x, float y) {
    __half2 h; h.x = __float2half(x); h.y = __float2half(y);
    return *(uint32_t*)&h;
}

// ---------------- counts / starts ------------------------------------------
__global__ void count_kernel(const int* __restrict__ batch)
{
    __shared__ int s[BG];
    int t = threadIdx.x;
    if (t < BG) s[t] = 0;
    __syncthreads();
    for (int i = t; i < NN; i += blockDim.x) atomicAdd(&s[batch[i]], 1);
    __syncthreads();
    if (t == 0) {
        int acc = 0;
        for (int b = 0; b < BG; b++) { g_starts[b] = acc; g_counts[b] = s[b]; acc += s[b]; }
    }
}

// ---------------- all 4 weights fp32 -> fp16, one launch ---------------------
#define NW0 (3 * H * H)
#define NW1 (H * H)
#define NW2 (4 * H * H)
#define NW3 (4 * H * H)
__global__ void convert_all_kernel(const float* __restrict__ s0, const float* __restrict__ s1,
                                   const float* __restrict__ s2, const float* __restrict__ s3,
                                   __half* __restrict__ d0, __half* __restrict__ d1,
                                   __half* __restrict__ d2, __half* __restrict__ d3)
{
    int i = blockIdx.x * blockDim.x + threadIdx.x;
    if (i < NW0)                          d0[i] = __float2half(s0[i]);
    else if (i < NW0 + NW1)               d1[i - NW0] = __float2half(s1[i - NW0]);
    else if (i < NW0 + NW1 + NW2)         d2[i - NW0 - NW1] = __float2half(s2[i - NW0 - NW1]);
    else if (i < NW0 + NW1 + NW2 + NW3)   d3[i - NW0 - NW1 - NW2] = __float2half(s3[i - NW0 - NW1 - NW2]);
}

// ---------------- GraphNorm (8-way row-parallel) ----------------------------
__global__ void graphnorm_kernel(const float* __restrict__ in,
                                 const float* __restrict__ w,
                                 const float* __restrict__ bias,
                                 __half* __restrict__ oh)
{
    int b = blockIdx.x;
    int c = g_counts[b];
    long s = g_starts[b];
    if (c == 0) return;
    int t = threadIdx.x;
    int f = blockIdx.y * 32 + (t & 31);
    int rl = t >> 5;

    __shared__ float ssum[8][33], ssq[8][33], smean[32], sinv[32];

    float sum = 0.f, sq = 0.f;
    for (int i = rl; i < c; i += 8) {
        float v = in[(s + i) * H + f];
        sum += v; sq += v * v;
    }
    ssum[rl][t & 31] = sum; ssq[rl][t & 31] = sq;
    __syncthreads();
    if (rl == 0) {
        float ts = 0.f, tq = 0.f;
        #pragma unroll
        for (int k = 0; k < 8; k++) { ts += ssum[k][t & 31]; tq += ssq[k][t & 31]; }
        float cf = (float)c;
        float mean = ts / cf;
        float var = fmaxf((tq - ts * ts / cf) / fmaxf(cf - 1.f, 1.f), 0.f);
        smean[t & 31] = mean;
        sinv[t & 31] = 1.f / (sqrtf(var) + 1e-5f);
    }
    __syncthreads();
    float mean = smean[t & 31], inv = sinv[t & 31];
    float ww = w[f], bb = bias[f];
    for (int i = rl; i < c; i += 8)
        oh[(s + i) * H + f] = __float2half(ww * ((in[(s + i) * H + f] - mean) * inv) + bb);
}

// ======================= HMMA GEMM (fp16, ldmatrix, 4-stage) ================
#define SROW   80
#define ARR_SZ (128 * SROW)        // 10240
#define STG_SZ (2 * ARR_SZ)        // 20480
#define GEMM_SMEM (4 * STG_SZ)     // 81920

template<int EPI>   // 1: bias+res->f32   2: gelu(bias)->fp16   3: bias->fp16
__global__ __launch_bounds__(256, 1) void hgemm_kernel(
    const __half* __restrict__ Ah, const __half* __restrict__ Bh,
    const float* __restrict__ bias, const float* __restrict__ res,
    float* __restrict__ Cf, __half* __restrict__ Ch,
    int Nc, int K)
{
    extern __shared__ char sm[];
    const int tid  = threadIdx.x;
    const int wid  = tid >> 5, lane = tid & 31;
    const int quad = lane >> 2, pair = lane & 3;
    const int m0 = blockIdx.y << 7, n0 = blockIdx.x << 7;
    const int wm = (wid & 1) << 6;
    const int wn = (wid >> 1) << 5;
    const uint32_t smb = smem_u32(sm);

    const int offA = ((lane & 7) + ((lane >> 3) & 1) * 8) * SROW + ((lane >> 4) & 1) * 16;
    const int offB = (((lane >> 4) & 1) * 8 + (lane & 7)) * SROW + ((lane >> 3) & 1) * 16;

    float acc[4][4][4];
    #pragma unroll
    for (int a = 0; a < 4; a++)
        #pragma unroll
        for (int b = 0; b < 4; b++)
            #pragma unroll
            for (int r = 0; r < 4; r++) acc[a][b][r] = 0.f;

    const int nchunk = K >> 5;

    auto load_chunk = [&](int stage, int k0) {
        uint32_t sb = smb + stage * STG_SZ;
        #pragma unroll
        for (int t = 0; t < 4; t++) {
            int task = tid + (t << 8);          // 0..1023
            int arr  = task >> 9;               // 0 = A, 1 = B
            int idx  = task & 511;
            int row  = idx >> 2, ch = idx & 3;
            int r0   = arr ? n0 : m0;
            const char* src = (const char*)(arr ? Bh : Ah) + ((size_t)(r0 + row) * K + k0 + ch * 8) * 2;
            uint32_t dst = sb + arr * ARR_SZ + row * SROW + ch * 16;
            CP_ASYNC16(dst, src);
        }
        CP_COMMIT();
    };

    load_chunk(0, 0);
    load_chunk(1, 32);
    for (int c = 0; c < nchunk; c++) {
        if (c + 2 < nchunk) load_chunk((c + 2) & 3, (c + 2) << 5);
        else                CP_COMMIT();
        CP_WAIT(2);
        __syncthreads();

        const int stg = (c & 3) * STG_SZ;
        #pragma unroll
        for (int ks = 0; ks < 2; ks++) {
            const int kb = ks * 32;
            uint32_t afh[4][4], bfh[2][4];
            #pragma unroll
            for (int mt = 0; mt < 4; mt++)
                LDSM4(afh[mt], smb + stg + (wm + mt * 16) * SROW + kb + offA);
            #pragma unroll
            for (int jp = 0; jp < 2; jp++)
                LDSM4(bfh[jp], smb + stg + ARR_SZ + (wn + jp * 16) * SROW + kb + offB);
            #pragma unroll
            for (int mt = 0; mt < 4; mt++)
                #pragma unroll
                for (int nt = 0; nt < 4; nt++)
                    mma16816(acc[mt][nt], afh[mt], &bfh[nt >> 1][(nt & 1) * 2]);
        }
    }

    // ---- epilogue ----
    #pragma unroll
    for (int mt = 0; mt < 4; mt++) {
        int row0 = m0 + wm + mt * 16 + quad;
        int row1 = row0 + 8;
        #pragma unroll
        for (int nt = 0; nt < 4; nt++) {
            int col = n0 + wn + nt * 8 + pair * 2;
            float b0v = bias[col], b1v = bias[col + 1];
            float v00 = acc[mt][nt][0] + b0v, v01 = acc[mt][nt][1] + b1v;
            float v10 = acc[mt][nt][2] + b0v, v11 = acc[mt][nt][3] + b1v;
            if (EPI == 2) {
                v00 = 0.5f * v00 * (1.f + erff(v00 * 0.70710678118654752f));
                v01 = 0.5f * v01 * (1.f + erff(v01 * 0.70710678118654752f));
                v10 = 0.5f * v10 * (1.f + erff(v10 * 0.70710678118654752f));
                v11 = 0.5f * v11 * (1.f + erff(v11 * 0.70710678118654752f));
            }
            if (EPI == 2 || EPI == 3) {
                *(uint32_t*)&Ch[(size_t)row0 * Nc + col] = pack2(v00, v01);
                *(uint32_t*)&Ch[(size_t)row1 * Nc + col] = pack2(v10, v11);
            } else {
                v00 += res[(size_t)row0 * Nc + col];
                v01 += res[(size_t)row0 * Nc + col + 1];
                v10 += res[(size_t)row1 * Nc + col];
                v11 += res[(size_t)row1 * Nc + col + 1];
                *(float2*)(Cf + (size_t)row0 * Nc + col) = make_float2(v00, v01);
                *(float2*)(Cf + (size_t)row1 * Nc + col) = make_float2(v10, v11);
            }
        }
    }
}

// ================= tensor-core flash attention (fp16) =======================
// grid (8 qtiles, NHEADS, BG), 128 threads; KV double-buffered
#define AQH 0
#define AKV 5120               // buf b at AKV + b*10240: [KH 5120][VH 5120]
#define ATT_SMEM 25600

__global__ __launch_bounds__(128) void attn_kernel(
    const __half* __restrict__ qkv, __half* __restrict__ ctx)
{
    int b  = blockIdx.z, h = blockIdx.y, qt = blockIdx.x;
    int cc = g_counts[b];
    int s  = g_starts[b];
    int q0 = qt << 6;
    if (q0 >= cc) return;

    __shared__ alignas(128) char sm[ATT_SMEM];
    const uint32_t smb = smem_u32(sm);
    const int tid = threadIdx.x, w = tid >> 5, l = tid & 31;

    const int offA = ((l & 7) + ((l >> 3) & 1) * 8) * SROW + ((l >> 4) & 1) * 16;
    const int offB = (((l >> 4) & 1) * 8 + (l & 7)) * SROW + ((l >> 3) & 1) * 16;

    // ---- Q tile (64 x 32) ----
    {
        #pragma unroll
        for (int t = 0; t < 2; t++) {
            int idx = tid + (t << 7);           // 0..255
            int row = idx >> 2, seg = idx & 3;
            const __half* src = qkv + (size_t)(s + q0 + row) * (3 * H) + h * HD + seg * 8;
            uint32_t dst = smb + row * SROW + seg * 16;
            CP_ASYNC16Z(dst, src, (q0 + row < cc) ? 16u : 0u);
        }
        CP_COMMIT();
    }
    auto issue_kv = [&](int k0, int buf) {
        #pragma unroll
        for (int t = 0; t < 4; t++) {
            int task = tid + (t << 7);               // 0..511
            int arr = task >> 8, idx = task & 255;   // 0 K, 1 V
            int row = idx >> 2, seg = idx & 3;
            const __half* src = qkv + (size_t)(s + k0 + row) * (3 * H) + h * HD + (arr + 1) * H + seg * 8;
            uint32_t dst = smb + AKV + buf * 10240 + arr * 5120 + row * SROW + seg * 16;
            CP_ASYNC16Z(dst, src, (k0 + row < cc) ? 16u : 0u);
        }
        CP_COMMIT();
    };
    issue_kv(0, 0);
    CP_WAIT(0);
    __syncthreads();

    uint32_t qf[2][4];
    #pragma unroll
    for (int kc = 0; kc < 2; kc++)
        LDSM4(qf[kc], smb + (w * 16) * SROW + kc * 32 + offA);

    const float scale = 0.17677669529663687f;
    float m0 = -1e30f, m1 = -1e30f, ls0 = 0.f, ls1 = 0.f;
    float o[4][4];
    #pragma unroll
    for (int dt = 0; dt < 4; dt++)
        #pragma unroll
        for (int r = 0; r < 4; r++) o[dt][r] = 0.f;

    int nch = (cc - 1) / 64 + 1;
    for (int ci = 0; ci * 64 < cc; ci++) {
        int k0 = ci * 64;
        uint32_t kvb = smb + AKV + (ci & 1) * 10240;
        if (ci + 1 < nch) issue_kv(k0 + 64, (ci + 1) & 1);

        // ---- S = Q K^T ----
        float sc[8][4];
        #pragma unroll
        for (int j = 0; j < 8; j++)
            #pragma unroll
            for (int r = 0; r < 4; r++) sc[j][r] = 0.f;

        #pragma unroll
        for (int jp = 0; jp < 4; jp++) {
            #pragma unroll
            for (int kc = 0; kc < 2; kc++) {
                uint32_t kh[4];
                LDSM4(kh, kvb + (jp * 16) * SROW + kc * 32 + offB);
                mma16816(sc[2 * jp],     qf[kc], kh);
                mma16816(sc[2 * jp + 1], qf[kc], kh + 2);
            }
        }
        // ---- scale + mask ----
        int colb = k0 + 2 * (l & 3);
        #pragma unroll
        for (int j = 0; j < 8; j++) {
            int c0 = colb + j * 8, c1 = c0 + 1;
            sc[j][0] = (c0 < cc) ? sc[j][0] * scale : -1e9f;
            sc[j][1] = (c1 < cc) ? sc[j][1] * scale : -1e9f;
            sc[j][2] = (c0 < cc) ? sc[j][2] * scale : -1e9f;
            sc[j][3] = (c1 < cc) ? sc[j][3] * scale : -1e9f;
        }
        // ---- softmax update ----
        float mx0 = -1e30f, mx1 = -1e30f;
        #pragma unroll
        for (int j = 0; j < 8; j++) {
            mx0 = fmaxf(mx0, fmaxf(sc[j][0], sc[j][1]));
            mx1 = fmaxf(mx1, fmaxf(sc[j][2], sc[j][3]));
        }
        mx0 = fmaxf(mx0, __shfl_xor_sync(0xffffffffu, mx0, 1));
        mx0 = fmaxf(mx0, __shfl_xor_sync(0xffffffffu, mx0, 2));
        mx1 = fmaxf(mx1, __shfl_xor_sync(0xffffffffu, mx1, 1));
        mx1 = fmaxf(mx1, __shfl_xor_sync(0xffffffffu, mx1, 2));
        float nm0 = fmaxf(m0, mx0), nm1 = fmaxf(m1, mx1);
        float a0 = __expf(m0 - nm0), a1 = __expf(m1 - nm1);
        float ps0 = 0.f, ps1 = 0.f;
        #pragma unroll
        for (int j = 0; j < 8; j++) {
            sc[j][0] = __expf(sc[j][0] - nm0);
            sc[j][1] = __expf(sc[j][1] - nm0);
            sc[j][2] = __expf(sc[j][2] - nm1);
            sc[j][3] = __expf(sc[j][3] - nm1);
            ps0 += sc[j][0] + sc[j][1];
            ps1 += sc[j][2] + sc[j][3];
        }
        ls0 = ls0 * a0 + ps0;
        ls1 = ls1 * a1 + ps1;
        m0 = nm0; m1 = nm1;
        // ---- P fragments ----
        uint32_t pa[4][4];
        #pragma unroll
        for (int kc = 0; kc < 4; kc++) {
            int j = 2 * kc;
            pa[kc][0] = pack2(sc[j][0], sc[j][1]);
            pa[kc][1] = pack2(sc[j][2], sc[j][3]);
            pa[kc][2] = pack2(sc[j + 1][0], sc[j + 1][1]);
            pa[kc][3] = pack2(sc[j + 1][2], sc[j + 1][3]);
        }
        #pragma unroll
        for (int dt = 0; dt < 4; dt++) {
            o[dt][0] *= a0; o[dt][1] *= a0;
            o[dt][2] *= a1; o[dt][3] *= a1;
        }
        // ---- O += P V ----
        #pragma unroll
        for (int kc = 0; kc < 4; kc++) {
            uint32_t vhA[4], vhB[4];
            uint32_t a = kvb + 5120 + (kc * 16) * SROW + offA;
            LDSM4T(vhA, a);
            LDSM4T(vhB, a + 32);
            mma16816(o[0], pa[kc], vhA);
            mma16816(o[1], pa[kc], vhA + 2);
            mma16816(o[2], pa[kc], vhB);
            mma16816(o[3], pa[kc], vhB + 2);
        }
        if (ci + 1 < nch) CP_WAIT(0);
        __syncthreads();
    }

    // ---- finalize ----
    ls0 += __shfl_xor_sync(0xffffffffu, ls0, 1);
    ls0 += __shfl_xor_sync(0xffffffffu, ls0, 2);
    ls1 += __shfl_xor_sync(0xffffffffu, ls1, 1);
    ls1 += __shfl_xor_sync(0xffffffffu, ls1, 2);
    float inv0 = 1.f / ls0, inv1 = 1.f / ls1;
    int r0 = q0 + w * 16 + (l >> 2);
    int r1 = r0 + 8;
    #pragma unroll
    for (int dt = 0; dt < 4; dt++) {
        int d = h * HD + dt * 8 + 2 * (l & 3);
        if (r0 < cc)
            *(uint32_t*)&ctx[(size_t)(s + r0) * H + d] = pack2(o[dt][0] * inv0, o[dt][1] * inv0);
        if (r1 < cc)
            *(uint32_t*)&ctx[(size_t)(s + r1) * H + d] = pack2(o[dt][2] * inv1, o[dt][3] * inv1);
    }
}

// ======================= launch =============================================
extern "C" void kernel_launch(void* const* d_in, const int* in_sizes, int n_in,
                              void* d_out, int out_size)
{
    const float* x     = (const float*)d_in[0];
    const int*   batch = (const int*)d_in[1];
    int base = (n_in >= 15 && in_sizes[2] == 1) ? 3 : 2;
    const float* n1w = (const float*)d_in[base + 0];
    const float* n1b = (const float*)d_in[base + 1];
    const float* iw  = (const float*)d_in[base + 2];
    const float* ib  = (const float*)d_in[base + 3];
    const float* ow  = (const float*)d_in[base + 4];
    const float* ob  = (const float*)d_in[base + 5];
    const float* n2w = (const float*)d_in[base + 6];
    const float* n2b = (const float*)d_in[base + 7];
    const float* w1  = (const float*)d_in[base + 8];
    const float* b1  = (const float*)d_in[base + 9];
    const float* w2  = (const float*)d_in[base + 10];
    const float* b2  = (const float*)d_in[base + 11];
    float* out = (float*)d_out;

    cudaFuncSetAttribute(hgemm_kernel<1>, cudaFuncAttributeMaxDynamicSharedMemorySize, GEMM_SMEM);
    cudaFuncSetAttribute(hgemm_kernel<2>, cudaFuncAttributeMaxDynamicSharedMemorySize, GEMM_SMEM);
    cudaFuncSetAttribute(hgemm_kernel<3>, cudaFuncAttributeMaxDynamicSharedMemorySize, GEMM_SMEM);

    __half *p_xn, *p_qkv, *p_ctx, *p_xn2, *p_hid, *p_wq, *p_wo, *p_w1, *p_w2;
    float *p_xmid;
    cudaGetSymbolAddress((void**)&p_xn,   g_xn);
    cudaGetSymbolAddress((void**)&p_qkv,  g_qkv);
    cudaGetSymbolAddress((void**)&p_ctx,  g_ctx);
    cudaGetSymbolAddress((void**)&p_xmid, g_xmid);
    cudaGetSymbolAddress((void**)&p_xn2,  g_xn2);
    cudaGetSymbolAddress((void**)&p_hid,  g_hid);
    cudaGetSymbolAddress((void**)&p_wq,   g_wqkv);
    cudaGetSymbolAddress((void**)&p_wo,   g_wout);
    cudaGetSymbolAddress((void**)&p_w1,   g_w1);
    cudaGetSymbolAddress((void**)&p_w2,   g_w2);

    count_kernel<<<1, 256>>>(batch);
    convert_all_kernel<<<(NW0 + NW1 + NW2 + NW3 + 255) / 256, 256>>>(
        iw, ow, w1, w2, p_wq, p_wo, p_w1, p_w2);
    graphnorm_kernel<<<dim3(BG, 8), 256>>>(x, n1w, n1b, p_xn);

    hgemm_kernel<3><<<dim3(3 * H / 128, NN / 128), 256, GEMM_SMEM>>>(
        p_xn, p_wq, ib, nullptr, nullptr, p_qkv, 3 * H, H);

    attn_kernel<<<dim3(8, NHEADS, BG), 128>>>(p_qkv, p_ctx);

    hgemm_kernel<1><<<dim3(H / 128, NN / 128), 256, GEMM_SMEM>>>(
        p_ctx, p_wo, ob, x, p_xmid, nullptr, H, H);

    graphnorm_kernel<<<dim3(BG, 8), 256>>>(p_xmid, n2w, n2b, p_xn2);

    hgemm_kernel<2><<<dim3(4 * H / 128, NN / 128), 256, GEMM_SMEM>>>(
        p_xn2, p_w1, b1, nullptr, nullptr, p_hid, 4 * H, H);

    hgemm_kernel<1><<<dim3(H / 128, NN / 128), 256, GEMM_SMEM>>>(
        p_hid, p_w2, b2, p_xmid, out, nullptr, H, 4 * H);
}

// round 8
// speedup vs baseline: 4.6127x; 1.0720x over previous
#include <cuda_runtime.h>
#include <cuda_fp16.h>
#include <math.h>
#include <stdint.h>

#define NN      16384
#define BG      64
#define H       256
#define NHEADS  8
#define HD      32

// ======================= scratch (device globals) ===========================
__device__ __half g_xn [NN * H];
__device__ __half g_qkv[NN * 3 * H];
__device__ __half g_ctx[NN * H];
__device__ float  g_xmid[NN * H];
__device__ __half g_xn2[NN * H];
__device__ __half g_hid[NN * 4 * H];
__device__ __half g_wqkv[3 * H * H];
__device__ __half g_wout[H * H];
__device__ __half g_w1[4 * H * H];
__device__ __half g_w2[H * 4 * H];
__device__ int g_counts[BG];
__device__ int g_starts[BG];

__device__ __forceinline__ uint32_t smem_u32(const void* p) {
    uint32_t a;
    asm("{ .reg .u64 t; cvta.to.shared.u64 t, %1; cvt.u32.u64 %0, t; }" : "=r"(a) : "l"(p));
    return a;
}
#define CP_ASYNC16(dst, src) \
    asm volatile("cp.async.cg.shared.global [%0], [%1], 16;" :: "r"(dst), "l"(src))
#define CP_ASYNC16Z(dst, src, vbytes) \
    asm volatile("cp.async.cg.shared.global [%0], [%1], 16, %2;" :: "r"(dst), "l"(src), "r"(vbytes))
#define CP_COMMIT() asm volatile("cp.async.commit_group;" ::: "memory")
#define CP_WAIT(n)  asm volatile("cp.async.wait_group %0;" :: "n"(n) : "memory")

#define LDSM4(r, addr) \
    asm volatile("ldmatrix.sync.aligned.m8n8.x4.shared.b16 {%0,%1,%2,%3}, [%4];" \
        : "=r"((r)[0]), "=r"((r)[1]), "=r"((r)[2]), "=r"((r)[3]) : "r"(addr))
#define LDSM4T(r, addr) \
    asm volatile("ldmatrix.sync.aligned.m8n8.x4.trans.shared.b16 {%0,%1,%2,%3}, [%4];" \
        : "=r"((r)[0]), "=r"((r)[1]), "=r"((r)[2]), "=r"((r)[3]) : "r"(addr))

__device__ __forceinline__ void mma16816(float* c, const uint32_t* a, const uint32_t* b) {
    asm volatile("mma.sync.aligned.m16n8k16.row.col.f32.f16.f16.f32 "
        "{%0,%1,%2,%3}, {%4,%5,%6,%7}, {%8,%9}, {%0,%1,%2,%3};"
        : "+f"(c[0]), "+f"(c[1]), "+f"(c[2]), "+f"(c[3])
        : "r"(a[0]), "r"(a[1]), "r"(a[2]), "r"(a[3]), "r"(b[0]), "r"(b[1]));
}

__device__ __forceinline__ uint32_t pack2(float x, float y) {
    __half2 h; h.x = __float2half(x); h.y = __float2half(y);
    return *(uint32_t*)&h;
}

// ---------------- counts / starts ------------------------------------------
__global__ void count_kernel(const int* __restrict__ batch)
{
    __shared__ int s[BG];
    int t = threadIdx.x;
    if (t < BG) s[t] = 0;
    __syncthreads();
    for (int i = t; i < NN; i += blockDim.x) atomicAdd(&s[batch[i]], 1);
    __syncthreads();
    if (t == 0) {
        int acc = 0;
        for (int b = 0; b < BG; b++) { g_starts[b] = acc; g_counts[b] = s[b]; acc += s[b]; }
    }
}

// ---------------- all 4 weights fp32 -> fp16, one launch ---------------------
#define NW0 (3 * H * H)
#define NW1 (H * H)
#define NW2 (4 * H * H)
#define NW3 (4 * H * H)
__global__ void convert_all_kernel(const float* __restrict__ s0, const float* __restrict__ s1,
                                   const float* __restrict__ s2, const float* __restrict__ s3,
                                   __half* __restrict__ d0, __half* __restrict__ d1,
                                   __half* __restrict__ d2, __half* __restrict__ d3)
{
    int i = blockIdx.x * blockDim.x + threadIdx.x;
    if (i < NW0)                          d0[i] = __float2half(s0[i]);
    else if (i < NW0 + NW1)               d1[i - NW0] = __float2half(s1[i - NW0]);
    else if (i < NW0 + NW1 + NW2)         d2[i - NW0 - NW1] = __float2half(s2[i - NW0 - NW1]);
    else if (i < NW0 + NW1 + NW2 + NW3)   d3[i - NW0 - NW1 - NW2] = __float2half(s3[i - NW0 - NW1 - NW2]);
}

// ---------------- GraphNorm (8-way row-parallel) ----------------------------
__global__ void graphnorm_kernel(const float* __restrict__ in,
                                 const float* __restrict__ w,
                                 const float* __restrict__ bias,
                                 __half* __restrict__ oh)
{
    int b = blockIdx.x;
    int c = g_counts[b];
    long s = g_starts[b];
    if (c == 0) return;
    int t = threadIdx.x;
    int f = blockIdx.y * 32 + (t & 31);
    int rl = t >> 5;

    __shared__ float ssum[8][33], ssq[8][33], smean[32], sinv[32];

    float sum = 0.f, sq = 0.f;
    for (int i = rl; i < c; i += 8) {
        float v = in[(s + i) * H + f];
        sum += v; sq += v * v;
    }
    ssum[rl][t & 31] = sum; ssq[rl][t & 31] = sq;
    __syncthreads();
    if (rl == 0) {
        float ts = 0.f, tq = 0.f;
        #pragma unroll
        for (int k = 0; k < 8; k++) { ts += ssum[k][t & 31]; tq += ssq[k][t & 31]; }
        float cf = (float)c;
        float mean = ts / cf;
        float var = fmaxf((tq - ts * ts / cf) / fmaxf(cf - 1.f, 1.f), 0.f);
        smean[t & 31] = mean;
        sinv[t & 31] = 1.f / (sqrtf(var) + 1e-5f);
    }
    __syncthreads();
    float mean = smean[t & 31], inv = sinv[t & 31];
    float ww = w[f], bb = bias[f];
    for (int i = rl; i < c; i += 8)
        oh[(s + i) * H + f] = __float2half(ww * ((in[(s + i) * H + f] - mean) * inv) + bb);
}

// ======================= HMMA GEMM (fp16, ldmatrix, 3-stage, 2 CTA/SM) ======
#define SROW   80
#define ARR_SZ (128 * SROW)        // 10240
#define STG_SZ (2 * ARR_SZ)        // 20480
#define GEMM_SMEM (3 * STG_SZ)     // 61440  (x2 CTA = 122880 < 228KB)

template<int EPI>   // 1: bias+res->f32   2: gelu(bias)->fp16   3: bias->fp16
__global__ __launch_bounds__(256, 2) void hgemm_kernel(
    const __half* __restrict__ Ah, const __half* __restrict__ Bh,
    const float* __restrict__ bias, const float* __restrict__ res,
    float* __restrict__ Cf, __half* __restrict__ Ch,
    int Nc, int K)
{
    extern __shared__ char sm[];
    const int tid  = threadIdx.x;
    const int wid  = tid >> 5, lane = tid & 31;
    const int quad = lane >> 2, pair = lane & 3;
    const int m0 = blockIdx.y << 7, n0 = blockIdx.x << 7;
    const int wm = (wid & 1) << 6;
    const int wn = (wid >> 1) << 5;
    const uint32_t smb = smem_u32(sm);

    const int offA = ((lane & 7) + ((lane >> 3) & 1) * 8) * SROW + ((lane >> 4) & 1) * 16;
    const int offB = (((lane >> 4) & 1) * 8 + (lane & 7)) * SROW + ((lane >> 3) & 1) * 16;

    float acc[4][4][4];
    #pragma unroll
    for (int a = 0; a < 4; a++)
        #pragma unroll
        for (int b = 0; b < 4; b++)
            #pragma unroll
            for (int r = 0; r < 4; r++) acc[a][b][r] = 0.f;

    const int nchunk = K >> 5;

    auto load_chunk = [&](int stage, int k0) {
        uint32_t sb = smb + stage * STG_SZ;
        #pragma unroll
        for (int t = 0; t < 4; t++) {
            int task = tid + (t << 8);          // 0..1023
            int arr  = task >> 9;               // 0 = A, 1 = B
            int idx  = task & 511;
            int row  = idx >> 2, ch = idx & 3;
            int r0   = arr ? n0 : m0;
            const char* src = (const char*)(arr ? Bh : Ah) + ((size_t)(r0 + row) * K + k0 + ch * 8) * 2;
            uint32_t dst = sb + arr * ARR_SZ + row * SROW + ch * 16;
            CP_ASYNC16(dst, src);
        }
        CP_COMMIT();
    };

    load_chunk(0, 0);
    load_chunk(1, 32);
    int stage = 0;
    for (int c = 0; c < nchunk; c++) {
        if (c + 2 < nchunk) {
            int ls = stage + 2; if (ls >= 3) ls -= 3;
            load_chunk(ls, (c + 2) << 5);
        } else CP_COMMIT();
        CP_WAIT(2);
        __syncthreads();

        const int stg = stage * STG_SZ;
        #pragma unroll
        for (int ks = 0; ks < 2; ks++) {
            const int kb = ks * 32;
            uint32_t afh[4][4], bfh[2][4];
            #pragma unroll
            for (int mt = 0; mt < 4; mt++)
                LDSM4(afh[mt], smb + stg + (wm + mt * 16) * SROW + kb + offA);
            #pragma unroll
            for (int jp = 0; jp < 2; jp++)
                LDSM4(bfh[jp], smb + stg + ARR_SZ + (wn + jp * 16) * SROW + kb + offB);
            #pragma unroll
            for (int mt = 0; mt < 4; mt++)
                #pragma unroll
                for (int nt = 0; nt < 4; nt++)
                    mma16816(acc[mt][nt], afh[mt], &bfh[nt >> 1][(nt & 1) * 2]);
        }
        __syncthreads();
        if (++stage >= 3) stage = 0;
    }

    // ---- epilogue ----
    #pragma unroll
    for (int mt = 0; mt < 4; mt++) {
        int row0 = m0 + wm + mt * 16 + quad;
        int row1 = row0 + 8;
        #pragma unroll
        for (int nt = 0; nt < 4; nt++) {
            int col = n0 + wn + nt * 8 + pair * 2;
            float b0v = bias[col], b1v = bias[col + 1];
            float v00 = acc[mt][nt][0] + b0v, v01 = acc[mt][nt][1] + b1v;
            float v10 = acc[mt][nt][2] + b0v, v11 = acc[mt][nt][3] + b1v;
            if (EPI == 2) {
                v00 = 0.5f * v00 * (1.f + erff(v00 * 0.70710678118654752f));
                v01 = 0.5f * v01 * (1.f + erff(v01 * 0.70710678118654752f));
                v10 = 0.5f * v10 * (1.f + erff(v10 * 0.70710678118654752f));
                v11 = 0.5f * v11 * (1.f + erff(v11 * 0.70710678118654752f));
            }
            if (EPI == 2 || EPI == 3) {
                *(uint32_t*)&Ch[(size_t)row0 * Nc + col] = pack2(v00, v01);
                *(uint32_t*)&Ch[(size_t)row1 * Nc + col] = pack2(v10, v11);
            } else {
                v00 += res[(size_t)row0 * Nc + col];
                v01 += res[(size_t)row0 * Nc + col + 1];
                v10 += res[(size_t)row1 * Nc + col];
                v11 += res[(size_t)row1 * Nc + col + 1];
                *(float2*)(Cf + (size_t)row0 * Nc + col) = make_float2(v00, v01);
                *(float2*)(Cf + (size_t)row1 * Nc + col) = make_float2(v10, v11);
            }
        }
    }
}

// ================= tensor-core flash attention (fp16) =======================
#define AQH 0
#define AKV 5120               // buf b at AKV + b*10240: [KH 5120][VH 5120]
#define ATT_SMEM 25600

__global__ __launch_bounds__(128) void attn_kernel(
    const __half* __restrict__ qkv, __half* __restrict__ ctx)
{
    int b  = blockIdx.z, h = blockIdx.y, qt = blockIdx.x;
    int cc = g_counts[b];
    int s  = g_starts[b];
    int q0 = qt << 6;
    if (q0 >= cc) return;

    __shared__ alignas(128) char sm[ATT_SMEM];
    const uint32_t smb = smem_u32(sm);
    const int tid = threadIdx.x, w = tid >> 5, l = tid & 31;

    const int offA = ((l & 7) + ((l >> 3) & 1) * 8) * SROW + ((l >> 4) & 1) * 16;
    const int offB = (((l >> 4) & 1) * 8 + (l & 7)) * SROW + ((l >> 3) & 1) * 16;

    {
        #pragma unroll
        for (int t = 0; t < 2; t++) {
            int idx = tid + (t << 7);
            int row = idx >> 2, seg = idx & 3;
            const __half* src = qkv + (size_t)(s + q0 + row) * (3 * H) + h * HD + seg * 8;
            uint32_t dst = smb + row * SROW + seg * 16;
            CP_ASYNC16Z(dst, src, (q0 + row < cc) ? 16u : 0u);
        }
        CP_COMMIT();
    }
    auto issue_kv = [&](int k0, int buf) {
        #pragma unroll
        for (int t = 0; t < 4; t++) {
            int task = tid + (t << 7);
            int arr = task >> 8, idx = task & 255;
            int row = idx >> 2, seg = idx & 3;
            const __half* src = qkv + (size_t)(s + k0 + row) * (3 * H) + h * HD + (arr + 1) * H + seg * 8;
            uint32_t dst = smb + AKV + buf * 10240 + arr * 5120 + row * SROW + seg * 16;
            CP_ASYNC16Z(dst, src, (k0 + row < cc) ? 16u : 0u);
        }
        CP_COMMIT();
    };
    issue_kv(0, 0);
    CP_WAIT(0);
    __syncthreads();

    uint32_t qf[2][4];
    #pragma unroll
    for (int kc = 0; kc < 2; kc++)
        LDSM4(qf[kc], smb + (w * 16) * SROW + kc * 32 + offA);

    const float scale = 0.17677669529663687f;
    float m0 = -1e30f, m1 = -1e30f, ls0 = 0.f, ls1 = 0.f;
    float o[4][4];
    #pragma unroll
    for (int dt = 0; dt < 4; dt++)
        #pragma unroll
        for (int r = 0; r < 4; r++) o[dt][r] = 0.f;

    int nch = (cc - 1) / 64 + 1;
    for (int ci = 0; ci * 64 < cc; ci++) {
        int k0 = ci * 64;
        uint32_t kvb = smb + AKV + (ci & 1) * 10240;
        if (ci + 1 < nch) issue_kv(k0 + 64, (ci + 1) & 1);

        float sc[8][4];
        #pragma unroll
        for (int j = 0; j < 8; j++)
            #pragma unroll
            for (int r = 0; r < 4; r++) sc[j][r] = 0.f;

        #pragma unroll
        for (int jp = 0; jp < 4; jp++) {
            #pragma unroll
            for (int kc = 0; kc < 2; kc++) {
                uint32_t kh[4];
                LDSM4(kh, kvb + (jp * 16) * SROW + kc * 32 + offB);
                mma16816(sc[2 * jp],     qf[kc], kh);
                mma16816(sc[2 * jp + 1], qf[kc], kh + 2);
            }
        }
        int colb = k0 + 2 * (l & 3);
        #pragma unroll
        for (int j = 0; j < 8; j++) {
            int c0 = colb + j * 8, c1 = c0 + 1;
            sc[j][0] = (c0 < cc) ? sc[j][0] * scale : -1e9f;
            sc[j][1] = (c1 < cc) ? sc[j][1] * scale : -1e9f;
            sc[j][2] = (c0 < cc) ? sc[j][2] * scale : -1e9f;
            sc[j][3] = (c1 < cc) ? sc[j][3] * scale : -1e9f;
        }
        float mx0 = -1e30f, mx1 = -1e30f;
        #pragma unroll
        for (int j = 0; j < 8; j++) {
            mx0 = fmaxf(mx0, fmaxf(sc[j][0], sc[j][1]));
            mx1 = fmaxf(mx1, fmaxf(sc[j][2], sc[j][3]));
        }
        mx0 = fmaxf(mx0, __shfl_xor_sync(0xffffffffu, mx0, 1));
        mx0 = fmaxf(mx0, __shfl_xor_sync(0xffffffffu, mx0, 2));
        mx1 = fmaxf(mx1, __shfl_xor_sync(0xffffffffu, mx1, 1));
        mx1 = fmaxf(mx1, __shfl_xor_sync(0xffffffffu, mx1, 2));
        float nm0 = fmaxf(m0, mx0), nm1 = fmaxf(m1, mx1);
        float a0 = __expf(m0 - nm0), a1 = __expf(m1 - nm1);
        float ps0 = 0.f, ps1 = 0.f;
        #pragma unroll
        for (int j = 0; j < 8; j++) {
            sc[j][0] = __expf(sc[j][0] - nm0);
            sc[j][1] = __expf(sc[j][1] - nm0);
            sc[j][2] = __expf(sc[j][2] - nm1);
            sc[j][3] = __expf(sc[j][3] - nm1);
            ps0 += sc[j][0] + sc[j][1];
            ps1 += sc[j][2] + sc[j][3];
        }
        ls0 = ls0 * a0 + ps0;
        ls1 = ls1 * a1 + ps1;
        m0 = nm0; m1 = nm1;
        uint32_t pa[4][4];
        #pragma unroll
        for (int kc = 0; kc < 4; kc++) {
            int j = 2 * kc;
            pa[kc][0] = pack2(sc[j][0], sc[j][1]);
            pa[kc][1] = pack2(sc[j][2], sc[j][3]);
            pa[kc][2] = pack2(sc[j + 1][0], sc[j + 1][1]);
            pa[kc][3] = pack2(sc[j + 1][2], sc[j + 1][3]);
        }
        #pragma unroll
        for (int dt = 0; dt < 4; dt++) {
            o[dt][0] *= a0; o[dt][1] *= a0;
            o[dt][2] *= a1; o[dt][3] *= a1;
        }
        #pragma unroll
        for (int kc = 0; kc < 4; kc++) {
            uint32_t vhA[4], vhB[4];
            uint32_t a = kvb + 5120 + (kc * 16) * SROW + offA;
            LDSM4T(vhA, a);
            LDSM4T(vhB, a + 32);
            mma16816(o[0], pa[kc], vhA);
            mma16816(o[1], pa[kc], vhA + 2);
            mma16816(o[2], pa[kc], vhB);
            mma16816(o[3], pa[kc], vhB + 2);
        }
        if (ci + 1 < nch) CP_WAIT(0);
        __syncthreads();
    }

    ls0 += __shfl_xor_sync(0xffffffffu, ls0, 1);
    ls0 += __shfl_xor_sync(0xffffffffu, ls0, 2);
    ls1 += __shfl_xor_sync(0xffffffffu, ls1, 1);
    ls1 += __shfl_xor_sync(0xffffffffu, ls1, 2);
    float inv0 = 1.f / ls0, inv1 = 1.f / ls1;
    int r0 = q0 + w * 16 + (l >> 2);
    int r1 = r0 + 8;
    #pragma unroll
    for (int dt = 0; dt < 4; dt++) {
        int d = h * HD + dt * 8 + 2 * (l & 3);
        if (r0 < cc)
            *(uint32_t*)&ctx[(size_t)(s + r0) * H + d] = pack2(o[dt][0] * inv0, o[dt][1] * inv0);
        if (r1 < cc)
            *(uint32_t*)&ctx[(size_t)(s + r1) * H + d] = pack2(o[dt][2] * inv1, o[dt][3] * inv1);
    }
}

// ======================= launch =============================================
extern "C" void kernel_launch(void* const* d_in, const int* in_sizes, int n_in,
                              void* d_out, int out_size)
{
    const float* x     = (const float*)d_in[0];
    const int*   batch = (const int*)d_in[1];
    int base = (n_in >= 15 && in_sizes[2] == 1) ? 3 : 2;
    const float* n1w = (const float*)d_in[base + 0];
    const float* n1b = (const float*)d_in[base + 1];
    const float* iw  = (const float*)d_in[base + 2];
    const float* ib  = (const float*)d_in[base + 3];
    const float* ow  = (const float*)d_in[base + 4];
    const float* ob  = (const float*)d_in[base + 5];
    const float* n2w = (const float*)d_in[base + 6];
    const float* n2b = (const float*)d_in[base + 7];
    const float* w1  = (const float*)d_in[base + 8];
    const float* b1  = (const float*)d_in[base + 9];
    const float* w2  = (const float*)d_in[base + 10];
    const float* b2  = (const float*)d_in[base + 11];
    float* out = (float*)d_out;

    cudaFuncSetAttribute(hgemm_kernel<1>, cudaFuncAttributeMaxDynamicSharedMemorySize, GEMM_SMEM);
    cudaFuncSetAttribute(hgemm_kernel<2>, cudaFuncAttributeMaxDynamicSharedMemorySize, GEMM_SMEM);
    cudaFuncSetAttribute(hgemm_kernel<3>, cudaFuncAttributeMaxDynamicSharedMemorySize, GEMM_SMEM);

    __half *p_xn, *p_qkv, *p_ctx, *p_xn2, *p_hid, *p_wq, *p_wo, *p_w1, *p_w2;
    float *p_xmid;
    cudaGetSymbolAddress((void**)&p_xn,   g_xn);
    cudaGetSymbolAddress((void**)&p_qkv,  g_qkv);
    cudaGetSymbolAddress((void**)&p_ctx,  g_ctx);
    cudaGetSymbolAddress((void**)&p_xmid, g_xmid);
    cudaGetSymbolAddress((void**)&p_xn2,  g_xn2);
    cudaGetSymbolAddress((void**)&p_hid,  g_hid);
    cudaGetSymbolAddress((void**)&p_wq,   g_wqkv);
    cudaGetSymbolAddress((void**)&p_wo,   g_wout);
    cudaGetSymbolAddress((void**)&p_w1,   g_w1);
    cudaGetSymbolAddress((void**)&p_w2,   g_w2);

    count_kernel<<<1, 256>>>(batch);
    convert_all_kernel<<<(NW0 + NW1 + NW2 + NW3 + 255) / 256, 256>>>(
        iw, ow, w1, w2, p_wq, p_wo, p_w1, p_w2);
    graphnorm_kernel<<<dim3(BG, 8), 256>>>(x, n1w, n1b, p_xn);

    hgemm_kernel<3><<<dim3(3 * H / 128, NN / 128), 256, GEMM_SMEM>>>(
        p_xn, p_wq, ib, nullptr, nullptr, p_qkv, 3 * H, H);

    attn_kernel<<<dim3(8, NHEADS, BG), 128>>>(p_qkv, p_ctx);

    hgemm_kernel<1><<<dim3(H / 128, NN / 128), 256, GEMM_SMEM>>>(
        p_ctx, p_wo, ob, x, p_xmid, nullptr, H, H);

    graphnorm_kernel<<<dim3(BG, 8), 256>>>(p_xmid, n2w, n2b, p_xn2);

    hgemm_kernel<2><<<dim3(4 * H / 128, NN / 128), 256, GEMM_SMEM>>>(
        p_xn2, p_w1, b1, nullptr, nullptr, p_hid, 4 * H, H);

    hgemm_kernel<1><<<dim3(H / 128, NN / 128), 256, GEMM_SMEM>>>(
        p_hid, p_w2, b2, p_xmid, out, nullptr, H, 4 * H);
}

// round 9
// speedup vs baseline: 4.8042x; 1.0415x over previous
#include <cuda_runtime.h>
#include <cuda_fp16.h>
#include <math.h>
#include <stdint.h>

#define NN      16384
#define BG      64
#define H       256
#define NHEADS  8
#define HD      32

// ======================= scratch (device globals) ===========================
__device__ __half g_xn [NN * H];
__device__ __half g_qkv[NN * 3 * H];
__device__ __half g_ctx[NN * H];
__device__ float  g_xmid[NN * H];
__device__ __half g_xn2[NN * H];
__device__ __half g_hid[NN * 4 * H];
__device__ __half g_wqkv[3 * H * H];
__device__ __half g_wout[H * H];
__device__ __half g_w1[4 * H * H];
__device__ __half g_w2[H * 4 * H];
__device__ int g_counts[BG];
__device__ int g_starts[BG];

__device__ __forceinline__ uint32_t smem_u32(const void* p) {
    uint32_t a;
    asm("{ .reg .u64 t; cvta.to.shared.u64 t, %1; cvt.u32.u64 %0, t; }" : "=r"(a) : "l"(p));
    return a;
}
#define CP_ASYNC16(dst, src) \
    asm volatile("cp.async.cg.shared.global [%0], [%1], 16;" :: "r"(dst), "l"(src))
#define CP_ASYNC16Z(dst, src, vbytes) \
    asm volatile("cp.async.cg.shared.global [%0], [%1], 16, %2;" :: "r"(dst), "l"(src), "r"(vbytes))
#define CP_COMMIT() asm volatile("cp.async.commit_group;" ::: "memory")
#define CP_WAIT(n)  asm volatile("cp.async.wait_group %0;" :: "n"(n) : "memory")

#define LDSM4(r, addr) \
    asm volatile("ldmatrix.sync.aligned.m8n8.x4.shared.b16 {%0,%1,%2,%3}, [%4];" \
        : "=r"((r)[0]), "=r"((r)[1]), "=r"((r)[2]), "=r"((r)[3]) : "r"(addr))
#define LDSM4T(r, addr) \
    asm volatile("ldmatrix.sync.aligned.m8n8.x4.trans.shared.b16 {%0,%1,%2,%3}, [%4];" \
        : "=r"((r)[0]), "=r"((r)[1]), "=r"((r)[2]), "=r"((r)[3]) : "r"(addr))

__device__ __forceinline__ void mma16816(float* c, const uint32_t* a, const uint32_t* b) {
    asm volatile("mma.sync.aligned.m16n8k16.row.col.f32.f16.f16.f32 "
        "{%0,%1,%2,%3}, {%4,%5,%6,%7}, {%8,%9}, {%0,%1,%2,%3};"
        : "+f"(c[0]), "+f"(c[1]), "+f"(c[2]), "+f"(c[3])
        : "r"(a[0]), "r"(a[1]), "r"(a[2]), "r"(a[3]), "r"(b[0]), "r"(b[1]));
}

__device__ __forceinline__ uint32_t pack2(float x, float y) {
    __half2 h; h.x = __float2half(x); h.y = __float2half(y);
    return *(uint32_t*)&h;
}

// ---------------- counts / starts ------------------------------------------
__global__ void count_kernel(const int* __restrict__ batch)
{
    __shared__ int s[BG];
    int t = threadIdx.x;
    if (t < BG) s[t] = 0;
    __syncthreads();
    for (int i = t; i < NN; i += blockDim.x) atomicAdd(&s[batch[i]], 1);
    __syncthreads();
    if (t == 0) {
        int acc = 0;
        for (int b = 0; b < BG; b++) { g_starts[b] = acc; g_counts[b] = s[b]; acc += s[b]; }
    }
}

// ---------------- all 4 weights fp32 -> fp16, one launch ---------------------
#define NW0 (3 * H * H)
#define NW1 (H * H)
#define NW2 (4 * H * H)
#define NW3 (4 * H * H)
__global__ void convert_all_kernel(const float* __restrict__ s0, const float* __restrict__ s1,
                                   const float* __restrict__ s2, const float* __restrict__ s3,
                                   __half* __restrict__ d0, __half* __restrict__ d1,
                                   __half* __restrict__ d2, __half* __restrict__ d3)
{
    int i = blockIdx.x * blockDim.x + threadIdx.x;
    if (i < NW0)                          d0[i] = __float2half(s0[i]);
    else if (i < NW0 + NW1)               d1[i - NW0] = __float2half(s1[i - NW0]);
    else if (i < NW0 + NW1 + NW2)         d2[i - NW0 - NW1] = __float2half(s2[i - NW0 - NW1]);
    else if (i < NW0 + NW1 + NW2 + NW3)   d3[i - NW0 - NW1 - NW2] = __float2half(s3[i - NW0 - NW1 - NW2]);
}

// ---------------- GraphNorm (8-way row-parallel) ----------------------------
__global__ void graphnorm_kernel(const float* __restrict__ in,
                                 const float* __restrict__ w,
                                 const float* __restrict__ bias,
                                 __half* __restrict__ oh)
{
    int b = blockIdx.x;
    int c = g_counts[b];
    long s = g_starts[b];
    if (c == 0) return;
    int t = threadIdx.x;
    int f = blockIdx.y * 32 + (t & 31);
    int rl = t >> 5;

    __shared__ float ssum[8][33], ssq[8][33], smean[32], sinv[32];

    float sum = 0.f, sq = 0.f;
    for (int i = rl; i < c; i += 8) {
        float v = in[(s + i) * H + f];
        sum += v; sq += v * v;
    }
    ssum[rl][t & 31] = sum; ssq[rl][t & 31] = sq;
    __syncthreads();
    if (rl == 0) {
        float ts = 0.f, tq = 0.f;
        #pragma unroll
        for (int k = 0; k < 8; k++) { ts += ssum[k][t & 31]; tq += ssq[k][t & 31]; }
        float cf = (float)c;
        float mean = ts / cf;
        float var = fmaxf((tq - ts * ts / cf) / fmaxf(cf - 1.f, 1.f), 0.f);
        smean[t & 31] = mean;
        sinv[t & 31] = 1.f / (sqrtf(var) + 1e-5f);
    }
    __syncthreads();
    float mean = smean[t & 31], inv = sinv[t & 31];
    float ww = w[f], bb = bias[f];
    for (int i = rl; i < c; i += 8)
        oh[(s + i) * H + f] = __float2half(ww * ((in[(s + i) * H + f] - mean) * inv) + bb);
}

// ======================= HMMA GEMM (fp16, ldmatrix, 4-stage, 2 CTA/SM) ======
// 4-stage ring => load stage (c+2)&3 never collides with a one-iteration-
// lagging warp's compute stage (c-1)&3  (distance 3 mod 4), so ONE barrier
// per chunk suffices.  81920B x 2 CTA = 163.8KB < 228KB.
#define SROW   80
#define ARR_SZ (128 * SROW)        // 10240
#define STG_SZ (2 * ARR_SZ)        // 20480
#define GEMM_SMEM (4 * STG_SZ)     // 81920

template<int EPI>   // 1: bias+res->f32   2: gelu(bias)->fp16   3: bias->fp16
__global__ __launch_bounds__(256, 2) void hgemm_kernel(
    const __half* __restrict__ Ah, const __half* __restrict__ Bh,
    const float* __restrict__ bias, const float* __restrict__ res,
    float* __restrict__ Cf, __half* __restrict__ Ch,
    int Nc, int K)
{
    extern __shared__ char sm[];
    const int tid  = threadIdx.x;
    const int wid  = tid >> 5, lane = tid & 31;
    const int quad = lane >> 2, pair = lane & 3;
    const int m0 = blockIdx.y << 7, n0 = blockIdx.x << 7;
    const int wm = (wid & 1) << 6;
    const int wn = (wid >> 1) << 5;
    const uint32_t smb = smem_u32(sm);

    const int offA = ((lane & 7) + ((lane >> 3) & 1) * 8) * SROW + ((lane >> 4) & 1) * 16;
    const int offB = (((lane >> 4) & 1) * 8 + (lane & 7)) * SROW + ((lane >> 3) & 1) * 16;

    float acc[4][4][4];
    #pragma unroll
    for (int a = 0; a < 4; a++)
        #pragma unroll
        for (int b = 0; b < 4; b++)
            #pragma unroll
            for (int r = 0; r < 4; r++) acc[a][b][r] = 0.f;

    const int nchunk = K >> 5;

    auto load_chunk = [&](int stage, int k0) {
        uint32_t sb = smb + stage * STG_SZ;
        #pragma unroll
        for (int t = 0; t < 4; t++) {
            int task = tid + (t << 8);          // 0..1023
            int arr  = task >> 9;               // 0 = A, 1 = B
            int idx  = task & 511;
            int row  = idx >> 2, ch = idx & 3;
            int r0   = arr ? n0 : m0;
            const char* src = (const char*)(arr ? Bh : Ah) + ((size_t)(r0 + row) * K + k0 + ch * 8) * 2;
            uint32_t dst = sb + arr * ARR_SZ + row * SROW + ch * 16;
            CP_ASYNC16(dst, src);
        }
        CP_COMMIT();
    };

    load_chunk(0, 0);
    load_chunk(1, 32);
    for (int c = 0; c < nchunk; c++) {
        if (c + 2 < nchunk) load_chunk((c + 2) & 3, (c + 2) << 5);
        else                CP_COMMIT();
        CP_WAIT(2);
        __syncthreads();

        const int stg = (c & 3) * STG_SZ;
        #pragma unroll
        for (int ks = 0; ks < 2; ks++) {
            const int kb = ks * 32;
            uint32_t afh[4][4], bfh[2][4];
            #pragma unroll
            for (int mt = 0; mt < 4; mt++)
                LDSM4(afh[mt], smb + stg + (wm + mt * 16) * SROW + kb + offA);
            #pragma unroll
            for (int jp = 0; jp < 2; jp++)
                LDSM4(bfh[jp], smb + stg + ARR_SZ + (wn + jp * 16) * SROW + kb + offB);
            #pragma unroll
            for (int mt = 0; mt < 4; mt++)
                #pragma unroll
                for (int nt = 0; nt < 4; nt++)
                    mma16816(acc[mt][nt], afh[mt], &bfh[nt >> 1][(nt & 1) * 2]);
        }
    }

    // ---- epilogue ----
    #pragma unroll
    for (int mt = 0; mt < 4; mt++) {
        int row0 = m0 + wm + mt * 16 + quad;
        int row1 = row0 + 8;
        #pragma unroll
        for (int nt = 0; nt < 4; nt++) {
            int col = n0 + wn + nt * 8 + pair * 2;
            float b0v = bias[col], b1v = bias[col + 1];
            float v00 = acc[mt][nt][0] + b0v, v01 = acc[mt][nt][1] + b1v;
            float v10 = acc[mt][nt][2] + b0v, v11 = acc[mt][nt][3] + b1v;
            if (EPI == 2) {
                v00 = 0.5f * v00 * (1.f + erff(v00 * 0.70710678118654752f));
                v01 = 0.5f * v01 * (1.f + erff(v01 * 0.70710678118654752f));
                v10 = 0.5f * v10 * (1.f + erff(v10 * 0.70710678118654752f));
                v11 = 0.5f * v11 * (1.f + erff(v11 * 0.70710678118654752f));
            }
            if (EPI == 2 || EPI == 3) {
                *(uint32_t*)&Ch[(size_t)row0 * Nc + col] = pack2(v00, v01);
                *(uint32_t*)&Ch[(size_t)row1 * Nc + col] = pack2(v10, v11);
            } else {
                v00 += res[(size_t)row0 * Nc + col];
                v01 += res[(size_t)row0 * Nc + col + 1];
                v10 += res[(size_t)row1 * Nc + col];
                v11 += res[(size_t)row1 * Nc + col + 1];
                *(float2*)(Cf + (size_t)row0 * Nc + col) = make_float2(v00, v01);
                *(float2*)(Cf + (size_t)row1 * Nc + col) = make_float2(v10, v11);
            }
        }
    }
}

// ================= tensor-core flash attention (fp16) =======================
#define AQH 0
#define AKV 5120               // buf b at AKV + b*10240: [KH 5120][VH 5120]
#define ATT_SMEM 25600

__global__ __launch_bounds__(128) void attn_kernel(
    const __half* __restrict__ qkv, __half* __restrict__ ctx)
{
    int b  = blockIdx.z, h = blockIdx.y, qt = blockIdx.x;
    int cc = g_counts[b];
    int s  = g_starts[b];
    int q0 = qt << 6;
    if (q0 >= cc) return;

    __shared__ alignas(128) char sm[ATT_SMEM];
    const uint32_t smb = smem_u32(sm);
    const int tid = threadIdx.x, w = tid >> 5, l = tid & 31;

    const int offA = ((l & 7) + ((l >> 3) & 1) * 8) * SROW + ((l >> 4) & 1) * 16;
    const int offB = (((l >> 4) & 1) * 8 + (l & 7)) * SROW + ((l >> 3) & 1) * 16;

    {
        #pragma unroll
        for (int t = 0; t < 2; t++) {
            int idx = tid + (t << 7);
            int row = idx >> 2, seg = idx & 3;
            const __half* src = qkv + (size_t)(s + q0 + row) * (3 * H) + h * HD + seg * 8;
            uint32_t dst = smb + row * SROW + seg * 16;
            CP_ASYNC16Z(dst, src, (q0 + row < cc) ? 16u : 0u);
        }
        CP_COMMIT();
    }
    auto issue_kv = [&](int k0, int buf) {
        #pragma unroll
        for (int t = 0; t < 4; t++) {
            int task = tid + (t << 7);
            int arr = task >> 8, idx = task & 255;
            int row = idx >> 2, seg = idx & 3;
            const __half* src = qkv + (size_t)(s + k0 + row) * (3 * H) + h * HD + (arr + 1) * H + seg * 8;
            uint32_t dst = smb + AKV + buf * 10240 + arr * 5120 + row * SROW + seg * 16;
            CP_ASYNC16Z(dst, src, (k0 + row < cc) ? 16u : 0u);
        }
        CP_COMMIT();
    };
    issue_kv(0, 0);
    CP_WAIT(0);
    __syncthreads();

    uint32_t qf[2][4];
    #pragma unroll
    for (int kc = 0; kc < 2; kc++)
        LDSM4(qf[kc], smb + (w * 16) * SROW + kc * 32 + offA);

    const float scale = 0.17677669529663687f;
    float m0 = -1e30f, m1 = -1e30f, ls0 = 0.f, ls1 = 0.f;
    float o[4][4];
    #pragma unroll
    for (int dt = 0; dt < 4; dt++)
        #pragma unroll
        for (int r = 0; r < 4; r++) o[dt][r] = 0.f;

    int nch = (cc - 1) / 64 + 1;
    for (int ci = 0; ci * 64 < cc; ci++) {
        int k0 = ci * 64;
        uint32_t kvb = smb + AKV + (ci & 1) * 10240;
        if (ci + 1 < nch) issue_kv(k0 + 64, (ci + 1) & 1);

        float sc[8][4];
        #pragma unroll
        for (int j = 0; j < 8; j++)
            #pragma unroll
            for (int r = 0; r < 4; r++) sc[j][r] = 0.f;

        #pragma unroll
        for (int jp = 0; jp < 4; jp++) {
            #pragma unroll
            for (int kc = 0; kc < 2; kc++) {
                uint32_t kh[4];
                LDSM4(kh, kvb + (jp * 16) * SROW + kc * 32 + offB);
                mma16816(sc[2 * jp],     qf[kc], kh);
                mma16816(sc[2 * jp + 1], qf[kc], kh + 2);
            }
        }
        int colb = k0 + 2 * (l & 3);
        #pragma unroll
        for (int j = 0; j < 8; j++) {
            int c0 = colb + j * 8, c1 = c0 + 1;
            sc[j][0] = (c0 < cc) ? sc[j][0] * scale : -1e9f;
            sc[j][1] = (c1 < cc) ? sc[j][1] * scale : -1e9f;
            sc[j][2] = (c0 < cc) ? sc[j][2] * scale : -1e9f;
            sc[j][3] = (c1 < cc) ? sc[j][3] * scale : -1e9f;
        }
        float mx0 = -1e30f, mx1 = -1e30f;
        #pragma unroll
        for (int j = 0; j < 8; j++) {
            mx0 = fmaxf(mx0, fmaxf(sc[j][0], sc[j][1]));
            mx1 = fmaxf(mx1, fmaxf(sc[j][2], sc[j][3]));
        }
        mx0 = fmaxf(mx0, __shfl_xor_sync(0xffffffffu, mx0, 1));
        mx0 = fmaxf(mx0, __shfl_xor_sync(0xffffffffu, mx0, 2));
        mx1 = fmaxf(mx1, __shfl_xor_sync(0xffffffffu, mx1, 1));
        mx1 = fmaxf(mx1, __shfl_xor_sync(0xffffffffu, mx1, 2));
        float nm0 = fmaxf(m0, mx0), nm1 = fmaxf(m1, mx1);
        float a0 = __expf(m0 - nm0), a1 = __expf(m1 - nm1);
        float ps0 = 0.f, ps1 = 0.f;
        #pragma unroll
        for (int j = 0; j < 8; j++) {
            sc[j][0] = __expf(sc[j][0] - nm0);
            sc[j][1] = __expf(sc[j][1] - nm0);
            sc[j][2] = __expf(sc[j][2] - nm1);
            sc[j][3] = __expf(sc[j][3] - nm1);
            ps0 += sc[j][0] + sc[j][1];
            ps1 += sc[j][2] + sc[j][3];
        }
        ls0 = ls0 * a0 + ps0;
        ls1 = ls1 * a1 + ps1;
        m0 = nm0; m1 = nm1;
        uint32_t pa[4][4];
        #pragma unroll
        for (int kc = 0; kc < 4; kc++) {
            int j = 2 * kc;
            pa[kc][0] = pack2(sc[j][0], sc[j][1]);
            pa[kc][1] = pack2(sc[j][2], sc[j][3]);
            pa[kc][2] = pack2(sc[j + 1][0], sc[j + 1][1]);
            pa[kc][3] = pack2(sc[j + 1][2], sc[j + 1][3]);
        }
        #pragma unroll
        for (int dt = 0; dt < 4; dt++) {
            o[dt][0] *= a0; o[dt][1] *= a0;
            o[dt][2] *= a1; o[dt][3] *= a1;
        }
        #pragma unroll
        for (int kc = 0; kc < 4; kc++) {
            uint32_t vhA[4], vhB[4];
            uint32_t a = kvb + 5120 + (kc * 16) * SROW + offA;
            LDSM4T(vhA, a);
            LDSM4T(vhB, a + 32);
            mma16816(o[0], pa[kc], vhA);
            mma16816(o[1], pa[kc], vhA + 2);
            mma16816(o[2], pa[kc], vhB);
            mma16816(o[3], pa[kc], vhB + 2);
        }
        if (ci + 1 < nch) CP_WAIT(0);
        __syncthreads();
    }

    ls0 += __shfl_xor_sync(0xffffffffu, ls0, 1);
    ls0 += __shfl_xor_sync(0xffffffffu, ls0, 2);
    ls1 += __shfl_xor_sync(0xffffffffu, ls1, 1);
    ls1 += __shfl_xor_sync(0xffffffffu, ls1, 2);
    float inv0 = 1.f / ls0, inv1 = 1.f / ls1;
    int r0 = q0 + w * 16 + (l >> 2);
    int r1 = r0 + 8;
    #pragma unroll
    for (int dt = 0; dt < 4; dt++) {
        int d = h * HD + dt * 8 + 2 * (l & 3);
        if (r0 < cc)
            *(uint32_t*)&ctx[(size_t)(s + r0) * H + d] = pack2(o[dt][0] * inv0, o[dt][1] * inv0);
        if (r1 < cc)
            *(uint32_t*)&ctx[(size_t)(s + r1) * H + d] = pack2(o[dt][2] * inv1, o[dt][3] * inv1);
    }
}

// ======================= launch =============================================
extern "C" void kernel_launch(void* const* d_in, const int* in_sizes, int n_in,
                              void* d_out, int out_size)
{
    const float* x     = (const float*)d_in[0];
    const int*   batch = (const int*)d_in[1];
    int base = (n_in >= 15 && in_sizes[2] == 1) ? 3 : 2;
    const float* n1w = (const float*)d_in[base + 0];
    const float* n1b = (const float*)d_in[base + 1];
    const float* iw  = (const float*)d_in[base + 2];
    const float* ib  = (const float*)d_in[base + 3];
    const float* ow  = (const float*)d_in[base + 4];
    const float* ob  = (const float*)d_in[base + 5];
    const float* n2w = (const float*)d_in[base + 6];
    const float* n2b = (const float*)d_in[base + 7];
    const float* w1  = (const float*)d_in[base + 8];
    const float* b1  = (const float*)d_in[base + 9];
    const float* w2  = (const float*)d_in[base + 10];
    const float* b2  = (const float*)d_in[base + 11];
    float* out = (float*)d_out;

    cudaFuncSetAttribute(hgemm_kernel<1>, cudaFuncAttributeMaxDynamicSharedMemorySize, GEMM_SMEM);
    cudaFuncSetAttribute(hgemm_kernel<2>, cudaFuncAttributeMaxDynamicSharedMemorySize, GEMM_SMEM);
    cudaFuncSetAttribute(hgemm_kernel<3>, cudaFuncAttributeMaxDynamicSharedMemorySize, GEMM_SMEM);

    __half *p_xn, *p_qkv, *p_ctx, *p_xn2, *p_hid, *p_wq, *p_wo, *p_w1, *p_w2;
    float *p_xmid;
    cudaGetSymbolAddress((void**)&p_xn,   g_xn);
    cudaGetSymbolAddress((void**)&p_qkv,  g_qkv);
    cudaGetSymbolAddress((void**)&p_ctx,  g_ctx);
    cudaGetSymbolAddress((void**)&p_xmid, g_xmid);
    cudaGetSymbolAddress((void**)&p_xn2,  g_xn2);
    cudaGetSymbolAddress((void**)&p_hid,  g_hid);
    cudaGetSymbolAddress((void**)&p_wq,   g_wqkv);
    cudaGetSymbolAddress((void**)&p_wo,   g_wout);
    cudaGetSymbolAddress((void**)&p_w1,   g_w1);
    cudaGetSymbolAddress((void**)&p_w2,   g_w2);

    count_kernel<<<1, 256>>>(batch);
    convert_all_kernel<<<(NW0 + NW1 + NW2 + NW3 + 255) / 256, 256>>>(
        iw, ow, w1, w2, p_wq, p_wo, p_w1, p_w2);
    graphnorm_kernel<<<dim3(BG, 8), 256>>>(x, n1w, n1b, p_xn);

    hgemm_kernel<3><<<dim3(3 * H / 128, NN / 128), 256, GEMM_SMEM>>>(
        p_xn, p_wq, ib, nullptr, nullptr, p_qkv, 3 * H, H);

    attn_kernel<<<dim3(8, NHEADS, BG), 128>>>(p_qkv, p_ctx);

    hgemm_kernel<1><<<dim3(H / 128, NN / 128), 256, GEMM_SMEM>>>(
        p_ctx, p_wo, ob, x, p_xmid, nullptr, H, H);

    graphnorm_kernel<<<dim3(BG, 8), 256>>>(p_xmid, n2w, n2b, p_xn2);

    hgemm_kernel<2><<<dim3(4 * H / 128, NN / 128), 256, GEMM_SMEM>>>(
        p_xn2, p_w1, b1, nullptr, nullptr, p_hid, 4 * H, H);

    hgemm_kernel<1><<<dim3(H / 128, NN / 128), 256, GEMM_SMEM>>>(
        p_hid, p_w2, b2, p_xmid, out, nullptr, H, 4 * H);
}